// round 10
// baseline (speedup 1.0000x reference)
#include <cuda_runtime.h>
#include <cuda_bf16.h>
#include <math.h>
#include <stdint.h>

#define NN   20000
#define EE   320000
#define DIN  128
#define HH   256
#define LL   2
#define GG   32
#define NREL 6

// ---------------- device scratch ----------------
__device__ float g_x[2 * NN * HH];                  // fp32 residual carrier
__device__ float g_accb[2 * NN * HH];               // layer GEMM output
__device__ __nv_bfloat16 g_xcat[2 * NN * 1024];     // [x(256) | agg0 | agg1 | agg2] per row
__device__ __nv_bfloat16 g_inb[2 * NN * DIN];       // bf16 raw inputs
__device__ __nv_bfloat16 g_web[2 * HH * DIN];       // emb weights [t][n][k]
__device__ __nv_bfloat16 g_wcat2[LL * 2 * HH * 1024]; // stacked layer B [lt][n(256)][k(1024)]
__device__ float g_blsum[LL * 2 * HH];
__device__ int   g_deg[NREL][NN];
__device__ int   g_rowptr[NREL][NN + 1];
__device__ int   g_cursor[NREL][NN];
__device__ int   g_col[NREL][EE];
__device__ float g_stats[2][2 * HH];
__device__ float g_pool[2][GG * HH];
__device__ int   g_pcnt[2][GG];
__device__ int   g_is64;

// ---------------- helpers ----------------
__device__ __forceinline__ int idx_at(const void* p, long long i, int is64) {
    return is64 ? (int)((const long long*)p)[i] : ((const int*)p)[i];
}
__device__ __forceinline__ uint32_t smem_u32(const void* p) {
    uint32_t a;
    asm("{ .reg .u64 t; cvta.to.shared.u64 t, %1; cvt.u32.u64 %0, t; }" : "=r"(a) : "l"(p));
    return a;
}
__device__ __forceinline__ void ldm_x4(uint32_t* r, uint32_t addr) {
    asm volatile("ldmatrix.sync.aligned.m8n8.x4.shared.b16 {%0,%1,%2,%3}, [%4];"
                 : "=r"(r[0]), "=r"(r[1]), "=r"(r[2]), "=r"(r[3]) : "r"(addr));
}
__device__ __forceinline__ void mma_bf16(float* c, const uint32_t* a, const uint32_t* b) {
    asm volatile("mma.sync.aligned.m16n8k16.row.col.f32.bf16.bf16.f32 "
                 "{%0,%1,%2,%3}, {%4,%5,%6,%7}, {%8,%9}, {%0,%1,%2,%3};"
                 : "+f"(c[0]), "+f"(c[1]), "+f"(c[2]), "+f"(c[3])
                 : "r"(a[0]), "r"(a[1]), "r"(a[2]), "r"(a[3]), "r"(b[0]), "r"(b[1]));
}
__device__ __forceinline__ void cp16(uint32_t dst, const void* src, int nbytes) {
    asm volatile("cp.async.cg.shared.global [%0], [%1], 16, %2;"
                 :: "r"(dst), "l"(src), "r"(nbytes));
}
__device__ __forceinline__ void addv(float* s, uint4 v) {
    const __nv_bfloat162* h = (const __nv_bfloat162*)&v;
#pragma unroll
    for (int u = 0; u < 4; u++) {
        float2 f = __bfloat1622float2(h[u]);
        s[2 * u] += f.x;
        s[2 * u + 1] += f.y;
    }
}

// ---------------- index dtype detection ----------------
__global__ void k_detect(const unsigned int* __restrict__ e) {
    __shared__ int any;
    if (threadIdx.x == 0) any = 0;
    __syncthreads();
    unsigned int v = 0;
    for (int i = threadIdx.x; i < 2048; i += blockDim.x)
        v |= e[(long long)i * 1874 + 1];
    if (v) any = 1;
    __syncthreads();
    if (threadIdx.x == 0) g_is64 = any ? 0 : 1;
}

// ---------------- CSR construction ----------------
__global__ void k_hist(const void* __restrict__ edge) {
    int is64 = g_is64;
    int gid = blockIdx.x * blockDim.x + threadIdx.x;
    if (gid >= NREL * EE) return;
    int r = gid / EE, e = gid - r * EE;
    int dst = idx_at(edge, ((long long)r * 2 + 1) * EE + e, is64);
    atomicAdd(&g_deg[r][dst], 1);
}

__global__ void __launch_bounds__(1024) k_scan() {
    int r = blockIdx.x;
    const int PER = 20;
    int tid = threadIdx.x;
    int lane = tid & 31, wid = tid >> 5;
    int start = tid * PER;
    int loc[PER];
    int sum = 0;
#pragma unroll
    for (int i = 0; i < PER; i++) {
        int idx = start + i;
        int v = (idx < NN) ? g_deg[r][idx] : 0;
        loc[i] = sum;
        sum += v;
    }
    __shared__ int wsum[32];
    int incl = sum;
#pragma unroll
    for (int o = 1; o < 32; o <<= 1) {
        int x = __shfl_up_sync(0xffffffffu, incl, o);
        if (lane >= o) incl += x;
    }
    if (lane == 31) wsum[wid] = incl;
    __syncthreads();
    if (wid == 0) {
        int v = wsum[lane];
#pragma unroll
        for (int o = 1; o < 32; o <<= 1) {
            int x = __shfl_up_sync(0xffffffffu, v, o);
            if (lane >= o) v += x;
        }
        wsum[lane] = v;
    }
    __syncthreads();
    int prefix = incl - sum + (wid ? wsum[wid - 1] : 0);
#pragma unroll
    for (int i = 0; i < PER; i++) {
        int idx = start + i;
        if (idx < NN) {
            int ex = prefix + loc[i];
            g_rowptr[r][idx] = ex;
            g_cursor[r][idx] = ex;
        }
    }
    if (tid == 1023) g_rowptr[r][NN] = prefix + sum;
}

__global__ void k_fill(const void* __restrict__ edge) {
    int is64 = g_is64;
    int gid = blockIdx.x * blockDim.x + threadIdx.x;
    if (gid >= NREL * EE) return;
    int r = gid / EE, e = gid - r * EE;
    int src = idx_at(edge, ((long long)r * 2 + 0) * EE + e, is64);
    int dst = idx_at(edge, ((long long)r * 2 + 1) * EE + e, is64);
    int slot = atomicAdd(&g_cursor[r][dst], 1);
    g_col[r][slot] = src;
}

// ---------------- input convert ----------------
__global__ void k_split(const float* __restrict__ x, __nv_bfloat16* __restrict__ b, int n) {
    int i = blockIdx.x * blockDim.x + threadIdx.x;
    if (i >= n) return;
    b[i] = __float2bfloat16(x[i]);
}

// ---------------- weight prep ----------------
__global__ void k_wprep(const float* __restrict__ We, const float* __restrict__ Wl,
                        const float* __restrict__ Wr, const float* __restrict__ bl) {
    int gid = blockIdx.x * blockDim.x + threadIdx.x;
    const int grp[2][3] = {{0, 1, 3}, {2, 4, 5}};
    if (gid < 2 * HH * DIN) {
        int t = gid >> 15, rem = gid & 32767, n = rem >> 7, k = rem & 127;
        g_web[t * HH * DIN + n * DIN + k] =
            __float2bfloat16(We[((long long)t * DIN + k) * HH + n]);
    }
    if (gid < LL * 2 * HH * 1024) {
        int lt = gid >> 18, rem = gid & 0x3FFFF, n = rem >> 10, k = rem & 1023;
        int layer = lt >> 1, t = lt & 1;
        float v;
        if (k < 256) {
            const float* W = Wr + (long long)layer * NREL * HH * HH;
            v = W[(long long)grp[t][0] * HH * HH + k * HH + n] +
                W[(long long)grp[t][1] * HH * HH + k * HH + n] +
                W[(long long)grp[t][2] * HH * HH + k * HH + n];
        } else {
            int q = (k - 256) >> 8, kk = (k - 256) & 255;
            int rel = grp[t][q];
            v = Wl[(((long long)layer * NREL + rel) * HH + kk) * HH + n];
        }
        g_wcat2[(long long)lt * HH * 1024 + n * 1024 + k] = __float2bfloat16(v);
    }
    if (gid < LL * 2 * HH) {
        int lt = gid >> 8, c = gid & 255;
        int layer = lt >> 1, t = lt & 1;
        const float* b = bl + (long long)layer * NREL * HH;
        g_blsum[lt * HH + c] = b[grp[t][0] * HH + c] + b[grp[t][1] * HH + c] +
                               b[grp[t][2] * HH + c];
    }
}

// ---------------- HMMA GEMM (bf16x1, cp.async double-buffered, fused BN stats) ----------------
#define SPAD 40
#define BUFB (128 * SPAD * 2)

__global__ void __launch_bounds__(256, 2) k_gemm(
    const __nv_bfloat16* __restrict__ A0, long long aZ,
    const __nv_bfloat16* __restrict__ B0, long long bZ,
    float* __restrict__ Cf0, long long cfZ,
    const float* __restrict__ bias0, int biasZ,
    __nv_bfloat16* __restrict__ Cb0, long long cbZ, int cbRow,
    float* __restrict__ stats0, int statsZ,
    int M, int K)
{
    __shared__ __nv_bfloat16 sA[2 * 128 * SPAD];
    __shared__ __nv_bfloat16 sB[2 * 128 * SPAD];
    __shared__ float ssum[128], ssq[128];
    int z = blockIdx.z;
    const __nv_bfloat16* A = A0 + (long long)z * aZ;
    const __nv_bfloat16* B = B0 + (long long)z * bZ;
    float* Cf = Cf0 + (long long)z * cfZ;
    const float* bias = bias0 + (long long)z * biasZ;
    __nv_bfloat16* Cb = Cb0 ? Cb0 + (long long)z * cbZ : nullptr;
    float* stats = stats0 ? stats0 + (long long)z * statsZ : nullptr;

    int tid = threadIdx.x, wid = tid >> 5, lane = tid & 31;
    long long bm = (long long)blockIdx.x * 128;
    int nb = blockIdx.y * 128;
    int wm = (wid & 3) * 32;
    int wn = (wid >> 2) * 64;
    uint32_t sbA = smem_u32(sA), sbB = smem_u32(sB);

    float acc[2][8][4];
#pragma unroll
    for (int i = 0; i < 2; i++)
#pragma unroll
        for (int j = 0; j < 8; j++)
#pragma unroll
            for (int q = 0; q < 4; q++) acc[i][j][q] = 0.0f;

    int a_row = (lane & 7) + ((lane >> 3) & 1) * 8;
    int a_col = (lane >> 4) * 8;
    int b_row = lane & 7;
    int b_col = (lane >> 3) * 8;
    int nch = K >> 5;

#define ISSUE_STAGE(c, buf) do {                                                   \
        _Pragma("unroll")                                                          \
        for (int i = tid; i < 512; i += 256) {                                     \
            int row = i >> 2, seg = (i & 3) << 3;                                  \
            uint32_t so = (buf) * BUFB + (uint32_t)(row * SPAD + seg) * 2;         \
            int av = (bm + row < M) ? 16 : 0;                                      \
            const __nv_bfloat16* ga = A + ((bm + row < M) ?                        \
                                           ((bm + row) * K + (c) * 32 + seg) : 0); \
            const __nv_bfloat16* gb = B + ((long long)(nb + row) * K + (c) * 32 + seg); \
            cp16(sbA + so, ga, av);                                                \
            cp16(sbB + so, gb, 16);                                                \
        }                                                                          \
        asm volatile("cp.async.commit_group;");                                    \
    } while (0)

    ISSUE_STAGE(0, 0);
    for (int c = 0; c < nch; c++) {
        if (c + 1 < nch) {
            ISSUE_STAGE(c + 1, (c + 1) & 1);
            asm volatile("cp.async.wait_group 1;");
        } else {
            asm volatile("cp.async.wait_group 0;");
        }
        __syncthreads();

        uint32_t bA = sbA + (c & 1) * BUFB, bB = sbB + (c & 1) * BUFB;
        uint32_t bf[8][4];
#pragma unroll
        for (int nt = 0; nt < 8; nt++)
            ldm_x4(bf[nt], bB + (uint32_t)((wn + nt * 8 + b_row) * SPAD + b_col) * 2);
#pragma unroll
        for (int ks = 0; ks < 2; ks++) {
            uint32_t af[2][4];
#pragma unroll
            for (int mt = 0; mt < 2; mt++)
                ldm_x4(af[mt], bA + (uint32_t)((wm + mt * 16 + a_row) * SPAD + ks * 16 + a_col) * 2);
#pragma unroll
            for (int mt = 0; mt < 2; mt++)
#pragma unroll
                for (int nt = 0; nt < 8; nt++)
                    mma_bf16(acc[mt][nt], af[mt], &bf[nt][ks * 2]);
        }
        __syncthreads();
    }
#undef ISSUE_STAGE

    // ---- epilogue (+ fused BN stats) ----
    if (stats) {
        for (int i = tid; i < 128; i += 256) { ssum[i] = 0.f; ssq[i] = 0.f; }
    }
    __syncthreads();
    int gidr = lane >> 2, tig = lane & 3;
#pragma unroll
    for (int mt = 0; mt < 2; mt++) {
        long long r0 = bm + wm + mt * 16 + gidr;
        long long r1 = r0 + 8;
#pragma unroll
        for (int nt = 0; nt < 8; nt++) {
            int cl = wn + nt * 8 + tig * 2;
            int col = nb + cl;
            float b0 = bias[col], b1 = bias[col + 1];
            if (r0 < M) {
                float v0 = acc[mt][nt][0] + b0, v1 = acc[mt][nt][1] + b1;
                *(float2*)&Cf[r0 * 256 + col] = make_float2(v0, v1);
                if (Cb) *(__nv_bfloat162*)&Cb[r0 * cbRow + col] = __floats2bfloat162_rn(v0, v1);
                if (stats) {
                    atomicAdd(&ssum[cl], v0); atomicAdd(&ssum[cl + 1], v1);
                    atomicAdd(&ssq[cl], v0 * v0); atomicAdd(&ssq[cl + 1], v1 * v1);
                }
            }
            if (r1 < M) {
                float v2 = acc[mt][nt][2] + b0, v3 = acc[mt][nt][3] + b1;
                *(float2*)&Cf[r1 * 256 + col] = make_float2(v2, v3);
                if (Cb) *(__nv_bfloat162*)&Cb[r1 * cbRow + col] = __floats2bfloat162_rn(v2, v3);
                if (stats) {
                    atomicAdd(&ssum[cl], v2); atomicAdd(&ssum[cl + 1], v3);
                    atomicAdd(&ssq[cl], v2 * v2); atomicAdd(&ssq[cl + 1], v3 * v3);
                }
            }
        }
    }
    if (stats) {
        __syncthreads();
        if (tid < 128) {
            atomicAdd(&stats[nb + tid], ssum[tid]);
            atomicAdd(&stats[HH + nb + tid], ssq[tid]);
        }
    }
}

// ---------------- gather-mean aggregation: raw features -> xcat aggregates ----------------
__global__ void k_agg() {
    int w = (blockIdx.x * blockDim.x + threadIdx.x) >> 5;
    int lane = threadIdx.x & 31;
    int t = blockIdx.y;
    if (w >= NN) return;
    const int grp[2][3] = {{0, 1, 3}, {2, 4, 5}};
    const int srcOf[6] = {0, 0, 0, 1, 1, 1};
    uint4* xc = (uint4*)g_xcat;                      // row = 128 uint4 (1024 bf16)
    uint4* orow = xc + ((long long)t * NN + w) * 128;
#pragma unroll
    for (int q = 0; q < 3; q++) {
        int r = grp[t][q];
        const uint4* base = xc + (long long)srcOf[r] * NN * 128;
        int b = g_rowptr[r][w], e = g_rowptr[r][w + 1];
        float s[8] = {0.f, 0.f, 0.f, 0.f, 0.f, 0.f, 0.f, 0.f};
        for (int j0 = b; j0 < e; j0 += 32) {
            int n = min(32, e - j0);
            int myc = (lane < n) ? g_col[r][j0 + lane] : 0;
            int k = 0;
            for (; k + 3 < n; k += 4) {
                int c0 = __shfl_sync(0xffffffffu, myc, k);
                int c1 = __shfl_sync(0xffffffffu, myc, k + 1);
                int c2 = __shfl_sync(0xffffffffu, myc, k + 2);
                int c3 = __shfl_sync(0xffffffffu, myc, k + 3);
                uint4 v0 = base[(long long)c0 * 128 + lane];
                uint4 v1 = base[(long long)c1 * 128 + lane];
                uint4 v2 = base[(long long)c2 * 128 + lane];
                uint4 v3 = base[(long long)c3 * 128 + lane];
                addv(s, v0); addv(s, v1); addv(s, v2); addv(s, v3);
            }
            for (; k < n; k++) {
                int c0 = __shfl_sync(0xffffffffu, myc, k);
                uint4 v0 = base[(long long)c0 * 128 + lane];
                addv(s, v0);
            }
        }
        float inv = (e > b) ? 1.0f / (float)(e - b) : 0.0f;
        uint4 o;
        __nv_bfloat162* oh = (__nv_bfloat162*)&o;
#pragma unroll
        for (int u = 0; u < 4; u++)
            oh[u] = __floats2bfloat162_rn(s[2 * u] * inv, s[2 * u + 1] * inv);
        orow[32 + q * 32 + lane] = o;
    }
}

// ---------------- batchnorm apply ----------------
__global__ void k_bnapply(const float* __restrict__ acc0, float* __restrict__ x0f,
                          __nv_bfloat16* __restrict__ xcat,
                          const float* __restrict__ st0, const float* __restrict__ gamma0,
                          const float* __restrict__ beta0, int resid, int writeX) {
    int t = blockIdx.y;
    long long off = (long long)t * NN * HH;
    const float* acc = acc0 + off;
    float* x = x0f + off;
    const float* st = st0 + t * 2 * HH;
    const float* gamma = gamma0 + t * HH;
    const float* beta  = beta0 + t * HH;
    int c = threadIdx.x;
    float meanA = st[c] * (1.0f / NN);
    float varA  = st[HH + c] * (1.0f / NN) - meanA * meanA;
    float varX  = varA * (1.0f / 9.0f);
    float rs    = rsqrtf(varX + 1e-5f);
    float scale = gamma[c] * rs * (1.0f / 3.0f);
    float shift = beta[c] - meanA * scale;
    for (int r = blockIdx.x; r < NN; r += gridDim.x) {
        long long i = (long long)r * HH + c;
        float y = fmaxf(fmaf(acc[i], scale, shift), 0.0f);
        float xn = resid ? (x[i] + y) : y;
        if (writeX) x[i] = xn;
        xcat[((long long)(t * NN + r)) * 1024 + c] = __float2bfloat16(xn);
    }
}

// ---------------- pooling + head ----------------
__global__ void k_pcnt(const void* __restrict__ bv, const void* __restrict__ bp) {
    int is64 = g_is64;
    int gid = blockIdx.x * blockDim.x + threadIdx.x;
    if (gid >= 2 * NN) return;
    int t = gid / NN, i = gid - t * NN;
    int g = t ? idx_at(bp, i, is64) : idx_at(bv, i, is64);
    atomicAdd(&g_pcnt[t][g], 1);
}

__global__ void k_pool(const __nv_bfloat16* __restrict__ xcat, const void* __restrict__ bv,
                       const void* __restrict__ bp, float* __restrict__ pool0) {
    int is64 = g_is64;
    int t = blockIdx.y;
    const void* batch = t ? bp : bv;
    float* pool = pool0 + t * GG * HH;
    int c = threadIdx.x;
    int r0 = blockIdx.x * 64;
    int r1 = min(r0 + 64, NN);
    float local = 0.f;
    int gprev = -1;
    for (int r = r0; r < r1; r++) {
        int g = idx_at(batch, r, is64);
        if (g != gprev) {
            if (gprev >= 0) atomicAdd(&pool[gprev * HH + c], local);
            local = 0.f;
            gprev = g;
        }
        local += __bfloat162float(xcat[((long long)(t * NN + r)) * 1024 + c]);
    }
    if (gprev >= 0) atomicAdd(&pool[gprev * HH + c], local);
}

__global__ void k_final(const float* __restrict__ Wo, const float* __restrict__ bo,
                        float* __restrict__ out) {
    int g = threadIdx.x >> 5, lane = threadIdx.x & 31;
    if (g >= GG) return;
    float cv = (float)max(g_pcnt[0][g], 1);
    float cp = (float)max(g_pcnt[1][g], 1);
    float s = 0.f;
    for (int c = lane; c < HH; c += 32)
        s += g_pool[0][g * HH + c] / cv * Wo[c] + g_pool[1][g * HH + c] / cp * Wo[HH + c];
#pragma unroll
    for (int off = 16; off; off >>= 1) s += __shfl_down_sync(0xffffffffu, s, off);
    if (lane == 0) out[g] = 1.0f / (1.0f + expf(-(s + bo[0])));
}

// ---------------- launcher ----------------
extern "C" void kernel_launch(void* const* d_in, const int* in_sizes, int n_in,
                              void* d_out, int out_size) {
    const float* x_vuln  = (const float*)d_in[0];
    const float* x_patch = (const float*)d_in[1];
    const float* W_emb   = (const float*)d_in[2];
    const float* b_emb   = (const float*)d_in[3];
    const float* W_l     = (const float*)d_in[4];
    const float* b_l     = (const float*)d_in[5];
    const float* W_r     = (const float*)d_in[6];
    const float* gamma   = (const float*)d_in[7];
    const float* beta    = (const float*)d_in[8];
    const float* W_out   = (const float*)d_in[9];
    const float* b_out   = (const float*)d_in[10];
    const void* edge     = d_in[11];
    const void* batch_v  = d_in[12];
    const void* batch_p  = d_in[13];
    float* out = (float*)d_out;

    void* p;
    cudaGetSymbolAddress(&p, g_x);     float* x0 = (float*)p;
    cudaGetSymbolAddress(&p, g_accb);  float* a0 = (float*)p;
    cudaGetSymbolAddress(&p, g_xcat);  __nv_bfloat16* xcat = (__nv_bfloat16*)p;
    cudaGetSymbolAddress(&p, g_inb);   __nv_bfloat16* inb = (__nv_bfloat16*)p;
    cudaGetSymbolAddress(&p, g_web);   __nv_bfloat16* web = (__nv_bfloat16*)p;
    cudaGetSymbolAddress(&p, g_wcat2); __nv_bfloat16* wcat2 = (__nv_bfloat16*)p;
    cudaGetSymbolAddress(&p, g_blsum); float* bls = (float*)p;
    cudaGetSymbolAddress(&p, g_deg);   void* degp = p;
    cudaGetSymbolAddress(&p, g_stats); float* stats = (float*)p;
    cudaGetSymbolAddress(&p, g_pool);  float* pool = (float*)p;
    cudaGetSymbolAddress(&p, g_pcnt);  void* pcnt = p;

    // index dtype detection + CSR build
    k_detect<<<1, 256>>>((const unsigned int*)edge);
    cudaMemsetAsync(degp, 0, sizeof(int) * NREL * NN, 0);
    k_hist<<<(NREL * EE + 255) / 256, 256>>>(edge);
    k_scan<<<NREL, 1024>>>();
    k_fill<<<(NREL * EE + 255) / 256, 256>>>(edge);

    // weight prep + input convert
    k_wprep<<<8192, 256>>>(W_emb, W_l, W_r, b_l);
    k_split<<<(NN * DIN + 255) / 256, 256>>>(x_vuln,  inb,            NN * DIN);
    k_split<<<(NN * DIN + 255) / 256, 256>>>(x_patch, inb + NN * DIN, NN * DIN);

    const int MB = (NN + 127) / 128;
    size_t xs = (size_t)NN * HH;
    // embedding GEMM (K=128): fp32 x + bf16 xcat[:,0:256], both types
    k_gemm<<<dim3(MB, 2, 2), 256>>>(inb, (long long)NN * DIN, web, (long long)HH * DIN,
                                    x0, (long long)xs, b_emb, HH,
                                    xcat, (long long)NN * 1024, 1024,
                                    nullptr, 0, NN, DIN);

    for (int layer = 0; layer < LL; layer++) {
        // gather-mean from raw features into xcat aggregate slots (both types)
        k_agg<<<dim3((NN * 32 + 255) / 256, 2), 256>>>();
        // one K=1024 GEMM: acc = [x|agg0|agg1|agg2] @ [Wr_sum;Wl0;Wl1;Wl2] + bias, fused stats
        cudaMemsetAsync(stats, 0, sizeof(float) * 2 * 2 * HH, 0);
        k_gemm<<<dim3(MB, 2, 2), 256>>>(xcat, (long long)NN * 1024,
                                        wcat2 + (size_t)(layer * 2) * HH * 1024, (long long)HH * 1024,
                                        a0, (long long)xs, bls + layer * 2 * HH, HH,
                                        nullptr, 0, 0,
                                        stats, 2 * HH, NN, 1024);
        // batchnorm + relu (+ residual)
        k_bnapply<<<dim3(256, 2), 256>>>(a0, x0, xcat, stats,
                                         gamma + layer * 2 * HH, beta + layer * 2 * HH,
                                         layer > 0, layer < LL - 1);
    }

    // pooling + head
    cudaMemsetAsync(pool, 0, sizeof(float) * 2 * GG * HH, 0);
    cudaMemsetAsync(pcnt, 0, sizeof(int) * 2 * GG, 0);
    k_pcnt<<<(2 * NN + 255) / 256, 256>>>(batch_v, batch_p);
    k_pool<<<dim3((NN + 63) / 64, 2), 256>>>(xcat, batch_v, batch_p, pool);
    k_final<<<1, 1024>>>(W_out, b_out, out);
}

// round 12
// speedup vs baseline: 1.3189x; 1.3189x over previous
#include <cuda_runtime.h>
#include <cuda_bf16.h>
#include <math.h>
#include <stdint.h>

#define NN   20000
#define EE   320000
#define DIN  128
#define HH   256
#define LL   2
#define GG   32
#define NREL 6

// ---------------- device scratch ----------------
__device__ float g_x[2 * NN * HH];
__device__ float g_accb[2 * NN * HH];
__device__ __nv_bfloat16 g_tmpb[NREL * NN * HH];     // neighbor GEMM outputs (bf16)
__device__ __nv_bfloat16 g_xb[2 * NN * HH];          // bf16 copy of x (GEMM A input)
__device__ __nv_bfloat16 g_inb[2 * NN * DIN];        // bf16 copy of raw inputs
__device__ __nv_bfloat16 g_web[2 * HH * DIN];        // emb weights [t][n][k]
__device__ __nv_bfloat16 g_wcat[LL * 2 * 1024 * HH]; // merged [l][t][1024 rows][k]
__device__ float g_blsum[LL * 2 * HH];
__device__ int   g_deg[NREL][NN];
__device__ int   g_rowptr[NREL][NN + 1];
__device__ int   g_cursor[NREL][NN];
__device__ int   g_col[NREL][EE];
__device__ float g_stats[2][2 * HH];
__device__ float g_pool[2][GG * HH];
__device__ int   g_pcnt[2][GG];
__device__ int   g_is64;

// ---------------- helpers ----------------
__device__ __forceinline__ int idx_at(const void* p, long long i, int is64) {
    return is64 ? (int)((const long long*)p)[i] : ((const int*)p)[i];
}
__device__ __forceinline__ uint32_t smem_u32(const void* p) {
    uint32_t a;
    asm("{ .reg .u64 t; cvta.to.shared.u64 t, %1; cvt.u32.u64 %0, t; }" : "=r"(a) : "l"(p));
    return a;
}
__device__ __forceinline__ void ldm_x4(uint32_t* r, uint32_t addr) {
    asm volatile("ldmatrix.sync.aligned.m8n8.x4.shared.b16 {%0,%1,%2,%3}, [%4];"
                 : "=r"(r[0]), "=r"(r[1]), "=r"(r[2]), "=r"(r[3]) : "r"(addr));
}
__device__ __forceinline__ void mma_bf16(float* c, const uint32_t* a, const uint32_t* b) {
    asm volatile("mma.sync.aligned.m16n8k16.row.col.f32.bf16.bf16.f32 "
                 "{%0,%1,%2,%3}, {%4,%5,%6,%7}, {%8,%9}, {%0,%1,%2,%3};"
                 : "+f"(c[0]), "+f"(c[1]), "+f"(c[2]), "+f"(c[3])
                 : "r"(a[0]), "r"(a[1]), "r"(a[2]), "r"(a[3]), "r"(b[0]), "r"(b[1]));
}
__device__ __forceinline__ void cp16(uint32_t dst, const void* src, int nbytes) {
    asm volatile("cp.async.cg.shared.global [%0], [%1], 16, %2;"
                 :: "r"(dst), "l"(src), "r"(nbytes));
}
__device__ __forceinline__ void addv(float* s, uint4 v) {
    const __nv_bfloat162* h = (const __nv_bfloat162*)&v;
#pragma unroll
    for (int u = 0; u < 4; u++) {
        float2 f = __bfloat1622float2(h[u]);
        s[2 * u] += f.x;
        s[2 * u + 1] += f.y;
    }
}

// ---------------- index dtype detection ----------------
__global__ void k_detect(const unsigned int* __restrict__ e) {
    __shared__ int any;
    if (threadIdx.x == 0) any = 0;
    __syncthreads();
    unsigned int v = 0;
    for (int i = threadIdx.x; i < 2048; i += blockDim.x)
        v |= e[(long long)i * 1874 + 1];
    if (v) any = 1;
    __syncthreads();
    if (threadIdx.x == 0) g_is64 = any ? 0 : 1;
}

// ---------------- CSR construction ----------------
__global__ void k_hist(const void* __restrict__ edge) {
    int is64 = g_is64;
    int gid = blockIdx.x * blockDim.x + threadIdx.x;
    if (gid >= NREL * EE) return;
    int r = gid / EE, e = gid - r * EE;
    int dst = idx_at(edge, ((long long)r * 2 + 1) * EE + e, is64);
    atomicAdd(&g_deg[r][dst], 1);
}

__global__ void __launch_bounds__(1024) k_scan() {
    int r = blockIdx.x;
    const int PER = 20;
    int tid = threadIdx.x;
    int lane = tid & 31, wid = tid >> 5;
    int start = tid * PER;
    int loc[PER];
    int sum = 0;
#pragma unroll
    for (int i = 0; i < PER; i++) {
        int idx = start + i;
        int v = (idx < NN) ? g_deg[r][idx] : 0;
        loc[i] = sum;
        sum += v;
    }
    __shared__ int wsum[32];
    int incl = sum;
#pragma unroll
    for (int o = 1; o < 32; o <<= 1) {
        int x = __shfl_up_sync(0xffffffffu, incl, o);
        if (lane >= o) incl += x;
    }
    if (lane == 31) wsum[wid] = incl;
    __syncthreads();
    if (wid == 0) {
        int v = wsum[lane];
#pragma unroll
        for (int o = 1; o < 32; o <<= 1) {
            int x = __shfl_up_sync(0xffffffffu, v, o);
            if (lane >= o) v += x;
        }
        wsum[lane] = v;
    }
    __syncthreads();
    int prefix = incl - sum + (wid ? wsum[wid - 1] : 0);
#pragma unroll
    for (int i = 0; i < PER; i++) {
        int idx = start + i;
        if (idx < NN) {
            int ex = prefix + loc[i];
            g_rowptr[r][idx] = ex;
            g_cursor[r][idx] = ex;
        }
    }
    if (tid == 1023) g_rowptr[r][NN] = prefix + sum;
}

__global__ void k_fill(const void* __restrict__ edge) {
    int is64 = g_is64;
    int gid = blockIdx.x * blockDim.x + threadIdx.x;
    if (gid >= NREL * EE) return;
    int r = gid / EE, e = gid - r * EE;
    int src = idx_at(edge, ((long long)r * 2 + 0) * EE + e, is64);
    int dst = idx_at(edge, ((long long)r * 2 + 1) * EE + e, is64);
    int slot = atomicAdd(&g_cursor[r][dst], 1);
    g_col[r][slot] = src;
}

// ---------------- input convert ----------------
__global__ void k_split(const float* __restrict__ x, __nv_bfloat16* __restrict__ b, int n) {
    int i = blockIdx.x * blockDim.x + threadIdx.x;
    if (i >= n) return;
    b[i] = __float2bfloat16(x[i]);
}

// ---------------- weight prep ----------------
__global__ void k_wprep(const float* __restrict__ We, const float* __restrict__ Wl,
                        const float* __restrict__ Wr, const float* __restrict__ bl) {
    int gid = blockIdx.x * blockDim.x + threadIdx.x;
    const int grp[2][3] = {{0, 1, 3}, {2, 4, 5}};
    if (gid < 2 * HH * DIN) {
        int t = gid >> 15, rem = gid & 32767, n = rem >> 7, k = rem & 127;
        g_web[t * HH * DIN + n * DIN + k] =
            __float2bfloat16(We[((long long)t * DIN + k) * HH + n]);
    }
    if (gid < LL * 2 * 1024 * HH) {
        int lt = gid >> 18, rem = gid & 0x3FFFF, row = rem >> 8, k = rem & 255;
        int layer = lt >> 1, t = lt & 1;
        float v;
        if (row < 256) {
            int n = row;
            const float* W = Wr + (long long)layer * NREL * HH * HH;
            v = W[(long long)grp[t][0] * HH * HH + k * HH + n] +
                W[(long long)grp[t][1] * HH * HH + k * HH + n] +
                W[(long long)grp[t][2] * HH * HH + k * HH + n];
        } else {
            int q = (row - 256) >> 8, n = row & 255;
            int rel = t * 3 + q;
            v = Wl[(((long long)layer * NREL + rel) * HH + k) * HH + n];
        }
        g_wcat[(long long)lt * 1024 * HH + row * HH + k] = __float2bfloat16(v);
    }
    if (gid < LL * 2 * HH) {
        int lt = gid >> 8, c = gid & 255;
        int layer = lt >> 1, t = lt & 1;
        const float* b = bl + (long long)layer * NREL * HH;
        g_blsum[lt * HH + c] = b[grp[t][0] * HH + c] + b[grp[t][1] * HH + c] +
                               b[grp[t][2] * HH + c];
    }
}

// ---------------- HMMA GEMM (bf16x1, cp.async double-buffered, z-batched types) ----------------
#define SPAD 40
#define BUFB (128 * SPAD * 2)

__global__ void __launch_bounds__(256, 2) k_gemm(
    const __nv_bfloat16* __restrict__ A0, long long aStr,
    const __nv_bfloat16* __restrict__ B0, long long bStr,
    float* __restrict__ Cf0, long long cfStr,
    const float* __restrict__ bias0, int biasStr,
    __nv_bfloat16* __restrict__ Cb0, long long cbzStr, long long cbStride,
    int selfN, int dualOut, int M, int K)
{
    __shared__ __nv_bfloat16 sA[2 * 128 * SPAD];
    __shared__ __nv_bfloat16 sB[2 * 128 * SPAD];
    int z = blockIdx.z;
    const __nv_bfloat16* A = A0 + (long long)z * aStr;
    const __nv_bfloat16* B = B0 + (long long)z * bStr;
    float* Cf = Cf0 ? Cf0 + (long long)z * cfStr : nullptr;
    const float* bias = bias0 ? bias0 + (long long)z * biasStr : nullptr;
    __nv_bfloat16* Cbz = Cb0 ? Cb0 + (long long)z * cbzStr : nullptr;

    int tid = threadIdx.x, wid = tid >> 5, lane = tid & 31;
    long long bm = (long long)blockIdx.x * 128;
    int nb = blockIdx.y * 128;
    int wm = (wid & 3) * 32;
    int wn = (wid >> 2) * 64;
    uint32_t sbA = smem_u32(sA), sbB = smem_u32(sB);

    float acc[2][8][4];
#pragma unroll
    for (int i = 0; i < 2; i++)
#pragma unroll
        for (int j = 0; j < 8; j++)
#pragma unroll
            for (int q = 0; q < 4; q++) acc[i][j][q] = 0.0f;

    int a_row = (lane & 7) + ((lane >> 3) & 1) * 8;
    int a_col = (lane >> 4) * 8;
    int b_row = lane & 31 & 7;
    int b_col = (lane >> 3) * 8;
    int nch = K >> 5;

#define ISSUE_STAGE(c, buf) do {                                                   \
        _Pragma("unroll")                                                          \
        for (int i = tid; i < 512; i += 256) {                                     \
            int row = i >> 2, seg = (i & 3) << 3;                                  \
            uint32_t so = (buf) * BUFB + (uint32_t)(row * SPAD + seg) * 2;         \
            int av = (bm + row < M) ? 16 : 0;                                      \
            const __nv_bfloat16* ga = A + ((bm + row < M) ?                        \
                                           ((bm + row) * K + (c) * 32 + seg) : 0); \
            const __nv_bfloat16* gb = B + ((long long)(nb + row) * K + (c) * 32 + seg); \
            cp16(sbA + so, ga, av);                                                \
            cp16(sbB + so, gb, 16);                                                \
        }                                                                          \
        asm volatile("cp.async.commit_group;");                                    \
    } while (0)

    ISSUE_STAGE(0, 0);
    for (int c = 0; c < nch; c++) {
        if (c + 1 < nch) {
            ISSUE_STAGE(c + 1, (c + 1) & 1);
            asm volatile("cp.async.wait_group 1;");
        } else {
            asm volatile("cp.async.wait_group 0;");
        }
        __syncthreads();

        uint32_t bA = sbA + (c & 1) * BUFB, bB = sbB + (c & 1) * BUFB;
        uint32_t bf[8][4];
#pragma unroll
        for (int nt = 0; nt < 8; nt++)
            ldm_x4(bf[nt], bB + (uint32_t)((wn + nt * 8 + b_row) * SPAD + b_col) * 2);
#pragma unroll
        for (int ks = 0; ks < 2; ks++) {
            uint32_t af[2][4];
#pragma unroll
            for (int mt = 0; mt < 2; mt++)
                ldm_x4(af[mt], bA + (uint32_t)((wm + mt * 16 + a_row) * SPAD + ks * 16 + a_col) * 2);
#pragma unroll
            for (int mt = 0; mt < 2; mt++)
#pragma unroll
                for (int nt = 0; nt < 8; nt++)
                    mma_bf16(acc[mt][nt], af[mt], &bf[nt][ks * 2]);
        }
        __syncthreads();
    }
#undef ISSUE_STAGE

    // ---- epilogue ----
    bool isSelf = (int)blockIdx.y < selfN;
    __nv_bfloat16* Cb = nullptr;
    if (Cbz) Cb = isSelf ? Cbz : (Cbz + (long long)((blockIdx.y >> 1) - 1) * cbStride);
    int gidr = lane >> 2, tig = lane & 3;
#pragma unroll
    for (int mt = 0; mt < 2; mt++) {
        long long r0 = bm + wm + mt * 16 + gidr;
        long long r1 = r0 + 8;
#pragma unroll
        for (int nt = 0; nt < 8; nt++) {
            int col = (blockIdx.y & 1) * 128 + wn + nt * 8 + tig * 2;
            float b0 = 0.f, b1 = 0.f;
            if (isSelf && bias) { b0 = bias[col]; b1 = bias[col + 1]; }
            if (r0 < M) {
                float v0 = acc[mt][nt][0] + b0, v1 = acc[mt][nt][1] + b1;
                if (isSelf) {
                    *(float2*)&Cf[r0 * 256 + col] = make_float2(v0, v1);
                    if (dualOut) *(__nv_bfloat162*)&Cb[r0 * 256 + col] = __floats2bfloat162_rn(v0, v1);
                } else {
                    *(__nv_bfloat162*)&Cb[r0 * 256 + col] = __floats2bfloat162_rn(v0, v1);
                }
            }
            if (r1 < M) {
                float v2 = acc[mt][nt][2] + b0, v3 = acc[mt][nt][3] + b1;
                if (isSelf) {
                    *(float2*)&Cf[r1 * 256 + col] = make_float2(v2, v3);
                    if (dualOut) *(__nv_bfloat162*)&Cb[r1 * 256 + col] = __floats2bfloat162_rn(v2, v3);
                } else {
                    *(__nv_bfloat162*)&Cb[r1 * 256 + col] = __floats2bfloat162_rn(v2, v3);
                }
            }
        }
    }
}

// ---------------- gather-mean aggregation + fused BN stats (y = dst type) ----------------
__global__ void k_agg(float* __restrict__ acc0, float* __restrict__ stats0) {
    __shared__ float bsum[HH], bsq[HH];
    int tid = threadIdx.x;
    int t = blockIdx.y;
    for (int i = tid; i < HH; i += 256) { bsum[i] = 0.f; bsq[i] = 0.f; }
    __syncthreads();

    int w = (blockIdx.x * blockDim.x + tid) >> 5;
    int lane = tid & 31;
    const int grp[2][3] = {{0, 1, 3}, {2, 4, 5}};
    float* acc = acc0 + (long long)t * NN * HH;
    float* stats = stats0 + t * 2 * HH;

    if (w < NN) {
        float s3[8] = {0.f, 0.f, 0.f, 0.f, 0.f, 0.f, 0.f, 0.f};
#pragma unroll
        for (int q = 0; q < 3; q++) {
            int r = grp[t][q];
            int b = g_rowptr[r][w], e = g_rowptr[r][w + 1];
            float s[8] = {0.f, 0.f, 0.f, 0.f, 0.f, 0.f, 0.f, 0.f};
            const uint4* base = (const uint4*)(g_tmpb + (long long)r * NN * HH);
            for (int j0 = b; j0 < e; j0 += 32) {
                int n = min(32, e - j0);
                int myc = (lane < n) ? g_col[r][j0 + lane] : 0;
                int k = 0;
                for (; k + 3 < n; k += 4) {
                    int c0 = __shfl_sync(0xffffffffu, myc, k);
                    int c1 = __shfl_sync(0xffffffffu, myc, k + 1);
                    int c2 = __shfl_sync(0xffffffffu, myc, k + 2);
                    int c3 = __shfl_sync(0xffffffffu, myc, k + 3);
                    uint4 v0 = base[(long long)c0 * 32 + lane];
                    uint4 v1 = base[(long long)c1 * 32 + lane];
                    uint4 v2 = base[(long long)c2 * 32 + lane];
                    uint4 v3 = base[(long long)c3 * 32 + lane];
                    addv(s, v0); addv(s, v1); addv(s, v2); addv(s, v3);
                }
                for (; k < n; k++) {
                    int c0 = __shfl_sync(0xffffffffu, myc, k);
                    uint4 v0 = base[(long long)c0 * 32 + lane];
                    addv(s, v0);
                }
            }
            float inv = (e > b) ? 1.0f / (float)(e - b) : 0.0f;
#pragma unroll
            for (int u = 0; u < 8; u++) s3[u] = fmaf(s[u], inv, s3[u]);
        }
        float4* arow = (float4*)(acc + (long long)w * HH + lane * 8);
        float4 o0 = arow[0], o1 = arow[1];
        float fin[8] = {o0.x + s3[0], o0.y + s3[1], o0.z + s3[2], o0.w + s3[3],
                        o1.x + s3[4], o1.y + s3[5], o1.z + s3[6], o1.w + s3[7]};
        arow[0] = make_float4(fin[0], fin[1], fin[2], fin[3]);
        arow[1] = make_float4(fin[4], fin[5], fin[6], fin[7]);
#pragma unroll
        for (int u = 0; u < 8; u++) {
            atomicAdd(&bsum[lane * 8 + u], fin[u]);
            atomicAdd(&bsq[lane * 8 + u], fin[u] * fin[u]);
        }
    }
    __syncthreads();
    for (int i = tid; i < HH; i += 256) {
        atomicAdd(&stats[i], bsum[i]);
        atomicAdd(&stats[HH + i], bsq[i]);
    }
}

// ---------------- batchnorm apply (y-batched types) ----------------
__global__ void k_bnapply(const float* __restrict__ acc0, float* __restrict__ x0,
                          __nv_bfloat16* __restrict__ xb0,
                          const float* __restrict__ st0, const float* __restrict__ gamma0,
                          const float* __restrict__ beta0, int resid, int writeX) {
    int t = blockIdx.y;
    long long off = (long long)t * NN * HH;
    const float* acc = acc0 + off;
    float* x = x0 + off;
    __nv_bfloat16* xb = xb0 + off;
    const float* st = st0 + t * 2 * HH;
    const float* gamma = gamma0 + t * HH;
    const float* beta  = beta0 + t * HH;
    int c = threadIdx.x;
    float meanA = st[c] * (1.0f / NN);
    float varA  = st[HH + c] * (1.0f / NN) - meanA * meanA;
    float varX  = varA * (1.0f / 9.0f);
    float rs    = rsqrtf(varX + 1e-5f);
    float scale = gamma[c] * rs * (1.0f / 3.0f);
    float shift = beta[c] - meanA * scale;
    for (int r = blockIdx.x; r < NN; r += gridDim.x) {
        long long i = (long long)r * HH + c;
        float y = fmaxf(fmaf(acc[i], scale, shift), 0.0f);
        float xn = resid ? (x[i] + y) : y;
        if (writeX) x[i] = xn;
        xb[i] = __float2bfloat16(xn);
    }
}

// ---------------- pooling + head ----------------
__global__ void k_pcnt(const void* __restrict__ bv, const void* __restrict__ bp) {
    int is64 = g_is64;
    int gid = blockIdx.x * blockDim.x + threadIdx.x;
    if (gid >= 2 * NN) return;
    int t = gid / NN, i = gid - t * NN;
    int g = t ? idx_at(bp, i, is64) : idx_at(bv, i, is64);
    atomicAdd(&g_pcnt[t][g], 1);
}

__global__ void k_pool(const __nv_bfloat16* __restrict__ xb0, const void* __restrict__ bv,
                       const void* __restrict__ bp, float* __restrict__ pool0) {
    int is64 = g_is64;
    int t = blockIdx.y;
    const __nv_bfloat16* xb = xb0 + (long long)t * NN * HH;
    const void* batch = t ? bp : bv;
    float* pool = pool0 + t * GG * HH;
    int c = threadIdx.x;
    int r0 = blockIdx.x * 64;
    int r1 = min(r0 + 64, NN);
    float local = 0.f;
    int gprev = -1;
    for (int r = r0; r < r1; r++) {
        int g = idx_at(batch, r, is64);
        if (g != gprev) {
            if (gprev >= 0) atomicAdd(&pool[gprev * HH + c], local);
            local = 0.f;
            gprev = g;
        }
        local += __bfloat162float(xb[(long long)r * HH + c]);
    }
    if (gprev >= 0) atomicAdd(&pool[gprev * HH + c], local);
}

__global__ void k_final(const float* __restrict__ Wo, const float* __restrict__ bo,
                        float* __restrict__ out) {
    int g = threadIdx.x >> 5, lane = threadIdx.x & 31;
    if (g >= GG) return;
    float cv = (float)max(g_pcnt[0][g], 1);
    float cp = (float)max(g_pcnt[1][g], 1);
    float s = 0.f;
    for (int c = lane; c < HH; c += 32)
        s += g_pool[0][g * HH + c] / cv * Wo[c] + g_pool[1][g * HH + c] / cp * Wo[HH + c];
#pragma unroll
    for (int off = 16; off; off >>= 1) s += __shfl_down_sync(0xffffffffu, s, off);
    if (lane == 0) out[g] = 1.0f / (1.0f + expf(-(s + bo[0])));
}

// ---------------- launcher ----------------
extern "C" void kernel_launch(void* const* d_in, const int* in_sizes, int n_in,
                              void* d_out, int out_size) {
    const float* x_vuln  = (const float*)d_in[0];
    const float* x_patch = (const float*)d_in[1];
    const float* W_emb   = (const float*)d_in[2];
    const float* b_emb   = (const float*)d_in[3];
    const float* W_l     = (const float*)d_in[4];
    const float* b_l     = (const float*)d_in[5];
    const float* W_r     = (const float*)d_in[6];
    const float* gamma   = (const float*)d_in[7];
    const float* beta    = (const float*)d_in[8];
    const float* W_out   = (const float*)d_in[9];
    const float* b_out   = (const float*)d_in[10];
    const void* edge     = d_in[11];
    const void* batch_v  = d_in[12];
    const void* batch_p  = d_in[13];
    float* out = (float*)d_out;

    void* p;
    cudaGetSymbolAddress(&p, g_x);     float* x0 = (float*)p;
    cudaGetSymbolAddress(&p, g_accb);  float* a0 = (float*)p;
    cudaGetSymbolAddress(&p, g_tmpb);  __nv_bfloat16* tmpb = (__nv_bfloat16*)p;
    cudaGetSymbolAddress(&p, g_xb);    __nv_bfloat16* xb = (__nv_bfloat16*)p;
    cudaGetSymbolAddress(&p, g_inb);   __nv_bfloat16* inb = (__nv_bfloat16*)p;
    cudaGetSymbolAddress(&p, g_web);   __nv_bfloat16* web = (__nv_bfloat16*)p;
    cudaGetSymbolAddress(&p, g_wcat);  __nv_bfloat16* wcat = (__nv_bfloat16*)p;
    cudaGetSymbolAddress(&p, g_blsum); float* bls = (float*)p;
    cudaGetSymbolAddress(&p, g_deg);   void* degp = p;
    cudaGetSymbolAddress(&p, g_stats); float* stats = (float*)p;
    cudaGetSymbolAddress(&p, g_pool);  float* pool = (float*)p;
    cudaGetSymbolAddress(&p, g_pcnt);  void* pcnt = p;

    // index dtype detection + CSR build
    k_detect<<<1, 256>>>((const unsigned int*)edge);
    cudaMemsetAsync(degp, 0, sizeof(int) * NREL * NN, 0);
    k_hist<<<(NREL * EE + 255) / 256, 256>>>(edge);
    k_scan<<<NREL, 1024>>>();
    k_fill<<<(NREL * EE + 255) / 256, 256>>>(edge);

    // weight prep + input convert
    k_wprep<<<4096, 256>>>(W_emb, W_l, W_r, b_l);
    k_split<<<(NN * DIN + 255) / 256, 256>>>(x_vuln,  inb,            NN * DIN);
    k_split<<<(NN * DIN + 255) / 256, 256>>>(x_patch, inb + NN * DIN, NN * DIN);

    const int MB = (NN + 127) / 128;
    size_t xs = (size_t)NN * HH;
    // embedding GEMMs (K=128), both types in one launch
    k_gemm<<<dim3(MB, 2, 2), 256>>>(inb, (long long)NN * DIN, web, (long long)HH * DIN,
                                    x0, (long long)xs, b_emb, HH,
                                    xb, (long long)xs, 0, 2, 1, NN, DIN);

    for (int layer = 0; layer < LL; layer++) {
        // merged self + 3-neighbor GEMM, both types in one launch
        k_gemm<<<dim3(MB, 8, 2), 256>>>(xb, (long long)xs,
                                        wcat + (size_t)(layer * 2) * 1024 * HH, (long long)1024 * HH,
                                        a0, (long long)xs, bls + layer * 2 * HH, HH,
                                        tmpb, (long long)3 * xs, (long long)xs,
                                        2, 0, NN, HH);
        // gather-mean + fused BN stats (both types)
        cudaMemsetAsync(stats, 0, sizeof(float) * 2 * 2 * HH, 0);
        k_agg<<<dim3((NN * 32 + 255) / 256, 2), 256>>>(a0, stats);
        // batchnorm + relu (+ residual)
        k_bnapply<<<dim3(256, 2), 256>>>(a0, x0, xb, stats,
                                         gamma + layer * 2 * HH, beta + layer * 2 * HH,
                                         layer > 0, layer < LL - 1);
    }

    // pooling + head
    cudaMemsetAsync(pool, 0, sizeof(float) * 2 * GG * HH, 0);
    cudaMemsetAsync(pcnt, 0, sizeof(int) * 2 * GG, 0);
    k_pcnt<<<(2 * NN + 255) / 256, 256>>>(batch_v, batch_p);
    k_pool<<<dim3((NN + 63) / 64, 2), 256>>>(xb, batch_v, batch_p, pool);
    k_final<<<1, 1024>>>(W_out, b_out, out);
}

// round 14
// speedup vs baseline: 1.4382x; 1.0905x over previous
#include <cuda_runtime.h>
#include <cuda_bf16.h>
#include <math.h>
#include <stdint.h>

#define NN   20000
#define EE   320000
#define DIN  128
#define HH   256
#define LL   2
#define GG   32
#define NREL 6

// ---------------- device scratch ----------------
__device__ float g_x[2 * NN * HH];
__device__ float g_accb[2 * NN * HH];
__device__ __nv_bfloat16 g_tmpb[NREL * NN * HH];
__device__ __nv_bfloat16 g_xb[2 * NN * HH];
__device__ __nv_bfloat16 g_inb[2 * NN * DIN];
__device__ __nv_bfloat16 g_web[2 * HH * DIN];
__device__ __nv_bfloat16 g_wcat[LL * 2 * 1024 * HH];
__device__ float g_blsum[LL * 2 * HH];
__device__ int   g_deg[NREL][NN];
__device__ int   g_rowptr[NREL][NN + 1];
__device__ int   g_cursor[NREL][NN];
__device__ int   g_col[NREL][EE];
struct ZeroBlk {
    float stats[LL * 2 * 2 * HH];
    float pool[2 * GG * HH];
    int   pcnt[2 * GG];
};
__device__ ZeroBlk g_z;
__device__ int g_is64;

// ---------------- helpers ----------------
__device__ __forceinline__ int idx_at(const void* p, long long i, int is64) {
    return is64 ? (int)((const long long*)p)[i] : ((const int*)p)[i];
}
__device__ __forceinline__ uint32_t smem_u32(const void* p) {
    uint32_t a;
    asm("{ .reg .u64 t; cvta.to.shared.u64 t, %1; cvt.u32.u64 %0, t; }" : "=r"(a) : "l"(p));
    return a;
}
__device__ __forceinline__ void ldm_x4(uint32_t* r, uint32_t addr) {
    asm volatile("ldmatrix.sync.aligned.m8n8.x4.shared.b16 {%0,%1,%2,%3}, [%4];"
                 : "=r"(r[0]), "=r"(r[1]), "=r"(r[2]), "=r"(r[3]) : "r"(addr));
}
__device__ __forceinline__ void mma_bf16(float* c, const uint32_t* a, const uint32_t* b) {
    asm volatile("mma.sync.aligned.m16n8k16.row.col.f32.bf16.bf16.f32 "
                 "{%0,%1,%2,%3}, {%4,%5,%6,%7}, {%8,%9}, {%0,%1,%2,%3};"
                 : "+f"(c[0]), "+f"(c[1]), "+f"(c[2]), "+f"(c[3])
                 : "r"(a[0]), "r"(a[1]), "r"(a[2]), "r"(a[3]), "r"(b[0]), "r"(b[1]));
}
__device__ __forceinline__ void cp16(uint32_t dst, const void* src, int nbytes) {
    asm volatile("cp.async.cg.shared.global [%0], [%1], 16, %2;"
                 :: "r"(dst), "l"(src), "r"(nbytes));
}
__device__ __forceinline__ void addv(float* s, uint4 v) {
    const __nv_bfloat162* h = (const __nv_bfloat162*)&v;
#pragma unroll
    for (int u = 0; u < 4; u++) {
        float2 f = __bfloat1622float2(h[u]);
        s[2 * u] += f.x;
        s[2 * u + 1] += f.y;
    }
}

// ---------------- combined prep: dtype detect + weight prep + input split ----------------
__global__ void k_prep(const unsigned int* __restrict__ e,
                       const float* __restrict__ xv, const float* __restrict__ xp,
                       const float* __restrict__ We, const float* __restrict__ Wl,
                       const float* __restrict__ Wr, const float* __restrict__ bl) {
    const int grp[2][3] = {{0, 1, 3}, {2, 4, 5}};
    int gid = blockIdx.x * blockDim.x + threadIdx.x;

    if (blockIdx.x == 0) {                     // index dtype detection
        __shared__ int any;
        if (threadIdx.x == 0) any = 0;
        __syncthreads();
        unsigned int v = 0;
        for (int i = threadIdx.x; i < 2048; i += blockDim.x)
            v |= e[(long long)i * 1874 + 1];
        if (v) any = 1;
        __syncthreads();
        if (threadIdx.x == 0) g_is64 = any ? 0 : 1;
    }

    if (gid < 2 * NN * DIN) {                  // input split
        float s = (gid < NN * DIN) ? xv[gid] : xp[gid - NN * DIN];
        g_inb[gid] = __float2bfloat16(s);
    }
    if (gid < 2 * HH * DIN) {                  // emb weights -> [t][n][k]
        int t = gid >> 15, rem = gid & 32767, n = rem >> 7, k = rem & 127;
        g_web[t * HH * DIN + n * DIN + k] =
            __float2bfloat16(We[((long long)t * DIN + k) * HH + n]);
    }
    if (gid < LL * 2 * 1024 * HH) {            // merged layer B
        int lt = gid >> 18, rem = gid & 0x3FFFF, row = rem >> 8, k = rem & 255;
        int layer = lt >> 1, t = lt & 1;
        float v;
        if (row < 256) {
            int n = row;
            const float* W = Wr + (long long)layer * NREL * HH * HH;
            v = W[(long long)grp[t][0] * HH * HH + k * HH + n] +
                W[(long long)grp[t][1] * HH * HH + k * HH + n] +
                W[(long long)grp[t][2] * HH * HH + k * HH + n];
        } else {
            int q = (row - 256) >> 8, n = row & 255;
            int rel = t * 3 + q;
            v = Wl[(((long long)layer * NREL + rel) * HH + k) * HH + n];
        }
        g_wcat[(long long)lt * 1024 * HH + row * HH + k] = __float2bfloat16(v);
    }
    if (gid < LL * 2 * HH) {                   // summed biases
        int lt = gid >> 8, c = gid & 255;
        int layer = lt >> 1, t = lt & 1;
        const float* b = bl + (long long)layer * NREL * HH;
        g_blsum[lt * HH + c] = b[grp[t][0] * HH + c] + b[grp[t][1] * HH + c] +
                               b[grp[t][2] * HH + c];
    }
}

// ---------------- CSR construction ----------------
__global__ void k_hist(const void* __restrict__ edge) {
    int is64 = g_is64;
    int gid = blockIdx.x * blockDim.x + threadIdx.x;
    if (gid >= NREL * EE) return;
    int r = gid / EE, e = gid - r * EE;
    int dst = idx_at(edge, ((long long)r * 2 + 1) * EE + e, is64);
    atomicAdd(&g_deg[r][dst], 1);
}

__global__ void __launch_bounds__(1024) k_scan() {
    int r = blockIdx.x;
    const int PER = 20;
    int tid = threadIdx.x;
    int lane = tid & 31, wid = tid >> 5;
    int start = tid * PER;
    int loc[PER];
    int sum = 0;
#pragma unroll
    for (int i = 0; i < PER; i++) {
        int idx = start + i;
        int v = (idx < NN) ? g_deg[r][idx] : 0;
        loc[i] = sum;
        sum += v;
    }
    __shared__ int wsum[32];
    int incl = sum;
#pragma unroll
    for (int o = 1; o < 32; o <<= 1) {
        int x = __shfl_up_sync(0xffffffffu, incl, o);
        if (lane >= o) incl += x;
    }
    if (lane == 31) wsum[wid] = incl;
    __syncthreads();
    if (wid == 0) {
        int v = wsum[lane];
#pragma unroll
        for (int o = 1; o < 32; o <<= 1) {
            int x = __shfl_up_sync(0xffffffffu, v, o);
            if (lane >= o) v += x;
        }
        wsum[lane] = v;
    }
    __syncthreads();
    int prefix = incl - sum + (wid ? wsum[wid - 1] : 0);
#pragma unroll
    for (int i = 0; i < PER; i++) {
        int idx = start + i;
        if (idx < NN) {
            int ex = prefix + loc[i];
            g_rowptr[r][idx] = ex;
            g_cursor[r][idx] = ex;
        }
    }
    if (tid == 1023) g_rowptr[r][NN] = prefix + sum;
}

__global__ void k_fill(const void* __restrict__ edge) {
    int is64 = g_is64;
    int gid = blockIdx.x * blockDim.x + threadIdx.x;
    if (gid >= NREL * EE) return;
    int r = gid / EE, e = gid - r * EE;
    int src = idx_at(edge, ((long long)r * 2 + 0) * EE + e, is64);
    int dst = idx_at(edge, ((long long)r * 2 + 1) * EE + e, is64);
    int slot = atomicAdd(&g_cursor[r][dst], 1);
    g_col[r][slot] = src;
}

// ---------------- HMMA GEMM (bf16x1, BK=64, cp.async double-buffered) ----------------
#define SPAD2 72
#define BUFB (128 * SPAD2 * 2)       // 18432 B per array per stage
#define SMEM_G (4 * BUFB)            // 73728 B

__global__ void __launch_bounds__(256, 2) k_gemm(
    const __nv_bfloat16* __restrict__ A0, long long aStr,
    const __nv_bfloat16* __restrict__ B0, long long bStr,
    float* __restrict__ Cf0, long long cfStr,
    const float* __restrict__ bias0, int biasStr,
    __nv_bfloat16* __restrict__ Cb0, long long cbzStr, long long cbStride,
    int selfN, int dualOut, int M, int K)
{
    extern __shared__ __nv_bfloat16 sm[];
    int z = blockIdx.z;
    const __nv_bfloat16* A = A0 + (long long)z * aStr;
    const __nv_bfloat16* B = B0 + (long long)z * bStr;
    float* Cf = Cf0 ? Cf0 + (long long)z * cfStr : nullptr;
    const float* bias = bias0 ? bias0 + (long long)z * biasStr : nullptr;
    __nv_bfloat16* Cbz = Cb0 ? Cb0 + (long long)z * cbzStr : nullptr;

    int tid = threadIdx.x, wid = tid >> 5, lane = tid & 31;
    long long bm = (long long)blockIdx.x * 128;
    int nb = blockIdx.y * 128;
    int wm = (wid & 3) * 32;
    int wn = (wid >> 2) * 64;
    uint32_t sbA = smem_u32(sm);
    uint32_t sbB = sbA + 2 * BUFB;

    float acc[2][8][4];
#pragma unroll
    for (int i = 0; i < 2; i++)
#pragma unroll
        for (int j = 0; j < 8; j++)
#pragma unroll
            for (int q = 0; q < 4; q++) acc[i][j][q] = 0.0f;

    int a_row = (lane & 7) + ((lane >> 3) & 1) * 8;
    int a_col = (lane >> 4) * 8;
    int b_row = lane & 7;
    int b_col = (lane >> 3) * 8;
    int nch = K >> 6;

#define ISSUE_STAGE(c, buf) do {                                                    \
        _Pragma("unroll")                                                           \
        for (int i = tid; i < 1024; i += 256) {                                     \
            int row = i >> 3, seg = (i & 7) << 3;                                   \
            uint32_t so = (buf) * BUFB + (uint32_t)(row * SPAD2 + seg) * 2;         \
            int av = (bm + row < M) ? 16 : 0;                                       \
            const __nv_bfloat16* ga = A + ((bm + row < M) ?                         \
                                           ((bm + row) * K + (c) * 64 + seg) : 0);  \
            const __nv_bfloat16* gb = B + ((long long)(nb + row) * K + (c) * 64 + seg); \
            cp16(sbA + so, ga, av);                                                 \
            cp16(sbB + so, gb, 16);                                                 \
        }                                                                           \
        asm volatile("cp.async.commit_group;");                                     \
    } while (0)

    ISSUE_STAGE(0, 0);
    for (int c = 0; c < nch; c++) {
        if (c + 1 < nch) {
            ISSUE_STAGE(c + 1, (c + 1) & 1);
            asm volatile("cp.async.wait_group 1;");
        } else {
            asm volatile("cp.async.wait_group 0;");
        }
        __syncthreads();

        uint32_t bA = sbA + (c & 1) * BUFB, bB = sbB + (c & 1) * BUFB;
#pragma unroll
        for (int half = 0; half < 2; half++) {
            uint32_t bf[8][4];
#pragma unroll
            for (int nt = 0; nt < 8; nt++)
                ldm_x4(bf[nt], bB + (uint32_t)((wn + nt * 8 + b_row) * SPAD2 +
                                               half * 32 + b_col) * 2);
#pragma unroll
            for (int ks = 0; ks < 2; ks++) {
                uint32_t af[2][4];
#pragma unroll
                for (int mt = 0; mt < 2; mt++)
                    ldm_x4(af[mt], bA + (uint32_t)((wm + mt * 16 + a_row) * SPAD2 +
                                                   half * 32 + ks * 16 + a_col) * 2);
#pragma unroll
                for (int mt = 0; mt < 2; mt++)
#pragma unroll
                    for (int nt = 0; nt < 8; nt++)
                        mma_bf16(acc[mt][nt], af[mt], &bf[nt][ks * 2]);
            }
        }
        __syncthreads();
    }
#undef ISSUE_STAGE

    // ---- epilogue ----
    bool isSelf = (int)blockIdx.y < selfN;
    __nv_bfloat16* Cb = nullptr;
    if (Cbz) Cb = isSelf ? Cbz : (Cbz + (long long)((blockIdx.y >> 1) - 1) * cbStride);
    int gidr = lane >> 2, tig = lane & 3;
#pragma unroll
    for (int mt = 0; mt < 2; mt++) {
        long long r0 = bm + wm + mt * 16 + gidr;
        long long r1 = r0 + 8;
#pragma unroll
        for (int nt = 0; nt < 8; nt++) {
            int col = (blockIdx.y & 1) * 128 + wn + nt * 8 + tig * 2;
            float b0 = 0.f, b1 = 0.f;
            if (isSelf && bias) { b0 = bias[col]; b1 = bias[col + 1]; }
            if (r0 < M) {
                float v0 = acc[mt][nt][0] + b0, v1 = acc[mt][nt][1] + b1;
                if (isSelf) {
                    *(float2*)&Cf[r0 * 256 + col] = make_float2(v0, v1);
                    if (dualOut) *(__nv_bfloat162*)&Cb[r0 * 256 + col] = __floats2bfloat162_rn(v0, v1);
                } else {
                    *(__nv_bfloat162*)&Cb[r0 * 256 + col] = __floats2bfloat162_rn(v0, v1);
                }
            }
            if (r1 < M) {
                float v2 = acc[mt][nt][2] + b0, v3 = acc[mt][nt][3] + b1;
                if (isSelf) {
                    *(float2*)&Cf[r1 * 256 + col] = make_float2(v2, v3);
                    if (dualOut) *(__nv_bfloat162*)&Cb[r1 * 256 + col] = __floats2bfloat162_rn(v2, v3);
                } else {
                    *(__nv_bfloat162*)&Cb[r1 * 256 + col] = __floats2bfloat162_rn(v2, v3);
                }
            }
        }
    }
}

// ---------------- gather-mean aggregation + fused BN stats (y = dst type) ----------------
__global__ void k_agg(float* __restrict__ acc0, float* __restrict__ stats0) {
    __shared__ float bsum[HH], bsq[HH];
    int tid = threadIdx.x;
    int t = blockIdx.y;
    for (int i = tid; i < HH; i += 256) { bsum[i] = 0.f; bsq[i] = 0.f; }
    __syncthreads();

    int w = (blockIdx.x * blockDim.x + tid) >> 5;
    int lane = tid & 31;
    const int grp[2][3] = {{0, 1, 3}, {2, 4, 5}};
    float* acc = acc0 + (long long)t * NN * HH;
    float* stats = stats0 + t * 2 * HH;

    if (w < NN) {
        float s3[8] = {0.f, 0.f, 0.f, 0.f, 0.f, 0.f, 0.f, 0.f};
#pragma unroll
        for (int q = 0; q < 3; q++) {
            int r = grp[t][q];
            int b = g_rowptr[r][w], e = g_rowptr[r][w + 1];
            float s[8] = {0.f, 0.f, 0.f, 0.f, 0.f, 0.f, 0.f, 0.f};
            const uint4* base = (const uint4*)(g_tmpb + (long long)r * NN * HH);
            for (int j0 = b; j0 < e; j0 += 32) {
                int n = min(32, e - j0);
                int myc = (lane < n) ? g_col[r][j0 + lane] : 0;
                int k = 0;
                for (; k + 3 < n; k += 4) {
                    int c0 = __shfl_sync(0xffffffffu, myc, k);
                    int c1 = __shfl_sync(0xffffffffu, myc, k + 1);
                    int c2 = __shfl_sync(0xffffffffu, myc, k + 2);
                    int c3 = __shfl_sync(0xffffffffu, myc, k + 3);
                    uint4 v0 = base[(long long)c0 * 32 + lane];
                    uint4 v1 = base[(long long)c1 * 32 + lane];
                    uint4 v2 = base[(long long)c2 * 32 + lane];
                    uint4 v3 = base[(long long)c3 * 32 + lane];
                    addv(s, v0); addv(s, v1); addv(s, v2); addv(s, v3);
                }
                for (; k < n; k++) {
                    int c0 = __shfl_sync(0xffffffffu, myc, k);
                    uint4 v0 = base[(long long)c0 * 32 + lane];
                    addv(s, v0);
                }
            }
            float inv = (e > b) ? 1.0f / (float)(e - b) : 0.0f;
#pragma unroll
            for (int u = 0; u < 8; u++) s3[u] = fmaf(s[u], inv, s3[u]);
        }
        float4* arow = (float4*)(acc + (long long)w * HH + lane * 8);
        float4 o0 = arow[0], o1 = arow[1];
        float fin[8] = {o0.x + s3[0], o0.y + s3[1], o0.z + s3[2], o0.w + s3[3],
                        o1.x + s3[4], o1.y + s3[5], o1.z + s3[6], o1.w + s3[7]};
        arow[0] = make_float4(fin[0], fin[1], fin[2], fin[3]);
        arow[1] = make_float4(fin[4], fin[5], fin[6], fin[7]);
#pragma unroll
        for (int u = 0; u < 8; u++) {
            atomicAdd(&bsum[lane * 8 + u], fin[u]);
            atomicAdd(&bsq[lane * 8 + u], fin[u] * fin[u]);
        }
    }
    __syncthreads();
    for (int i = tid; i < HH; i += 256) {
        atomicAdd(&stats[i], bsum[i]);
        atomicAdd(&stats[HH + i], bsq[i]);
    }
}

// ---------------- batchnorm apply (non-final layers) ----------------
__global__ void k_bnapply(const float* __restrict__ acc0, float* __restrict__ x0,
                          __nv_bfloat16* __restrict__ xb0,
                          const float* __restrict__ st0, const float* __restrict__ gamma0,
                          const float* __restrict__ beta0, int resid) {
    int t = blockIdx.y;
    long long off = (long long)t * NN * HH;
    const float* acc = acc0 + off;
    float* x = x0 + off;
    __nv_bfloat16* xb = xb0 + off;
    const float* st = st0 + t * 2 * HH;
    const float* gamma = gamma0 + t * HH;
    const float* beta  = beta0 + t * HH;
    int c = threadIdx.x;
    float meanA = st[c] * (1.0f / NN);
    float varA  = st[HH + c] * (1.0f / NN) - meanA * meanA;
    float varX  = varA * (1.0f / 9.0f);
    float rs    = rsqrtf(varX + 1e-5f);
    float scale = gamma[c] * rs * (1.0f / 3.0f);
    float shift = beta[c] - meanA * scale;
    for (int r = blockIdx.x; r < NN; r += gridDim.x) {
        long long i = (long long)r * HH + c;
        float y = fmaxf(fmaf(acc[i], scale, shift), 0.0f);
        float xn = resid ? (x[i] + y) : y;
        x[i] = xn;
        xb[i] = __float2bfloat16(xn);
    }
}

// ---------------- final layer: BN + residual + mean pool, fused ----------------
__global__ void k_bnpool(const float* __restrict__ acc0, const float* __restrict__ x0,
                         const float* __restrict__ st0, const float* __restrict__ gamma0,
                         const float* __restrict__ beta0,
                         const void* __restrict__ bv, const void* __restrict__ bp,
                         float* __restrict__ pool0) {
    int is64 = g_is64;
    int t = blockIdx.y;
    long long off = (long long)t * NN * HH;
    const float* acc = acc0 + off;
    const float* x = x0 + off;
    const float* st = st0 + t * 2 * HH;
    const void* batch = t ? bp : bv;
    float* pool = pool0 + t * GG * HH;
    int c = threadIdx.x;
    float meanA = st[c] * (1.0f / NN);
    float varA  = st[HH + c] * (1.0f / NN) - meanA * meanA;
    float rs    = rsqrtf(varA * (1.0f / 9.0f) + 1e-5f);
    float scale = gamma0[t * HH + c] * rs * (1.0f / 3.0f);
    float shift = beta0[t * HH + c] - meanA * scale;

    int r0 = blockIdx.x * 64;
    int r1 = min(r0 + 64, NN);
    float local = 0.f;
    int gprev = -1;
    for (int r = r0; r < r1; r++) {
        int g = idx_at(batch, r, is64);
        if (g != gprev) {
            if (gprev >= 0) atomicAdd(&pool[gprev * HH + c], local);
            local = 0.f;
            gprev = g;
        }
        long long i = (long long)r * HH + c;
        float y = fmaxf(fmaf(acc[i], scale, shift), 0.0f);
        local += x[i] + y;                       // resid always on in final layer (LL>=2)
    }
    if (gprev >= 0) atomicAdd(&pool[gprev * HH + c], local);
}

// ---------------- pcnt + head ----------------
__global__ void k_pcnt(const void* __restrict__ bv, const void* __restrict__ bp,
                       int* __restrict__ pcnt) {
    int is64 = g_is64;
    int gid = blockIdx.x * blockDim.x + threadIdx.x;
    if (gid >= 2 * NN) return;
    int t = gid / NN, i = gid - t * NN;
    int g = t ? idx_at(bp, i, is64) : idx_at(bv, i, is64);
    atomicAdd(&pcnt[t * GG + g], 1);
}

__global__ void k_final(const float* __restrict__ Wo, const float* __restrict__ bo,
                        const float* __restrict__ pool, const int* __restrict__ pcnt,
                        float* __restrict__ out) {
    int g = threadIdx.x >> 5, lane = threadIdx.x & 31;
    if (g >= GG) return;
    float cv = (float)max(pcnt[g], 1);
    float cp = (float)max(pcnt[GG + g], 1);
    float s = 0.f;
    for (int c = lane; c < HH; c += 32)
        s += pool[g * HH + c] / cv * Wo[c] + pool[GG * HH + g * HH + c] / cp * Wo[HH + c];
#pragma unroll
    for (int off = 16; off; off >>= 1) s += __shfl_down_sync(0xffffffffu, s, off);
    if (lane == 0) out[g] = 1.0f / (1.0f + expf(-(s + bo[0])));
}

// ---------------- launcher ----------------
extern "C" void kernel_launch(void* const* d_in, const int* in_sizes, int n_in,
                              void* d_out, int out_size) {
    const float* x_vuln  = (const float*)d_in[0];
    const float* x_patch = (const float*)d_in[1];
    const float* W_emb   = (const float*)d_in[2];
    const float* b_emb   = (const float*)d_in[3];
    const float* W_l     = (const float*)d_in[4];
    const float* b_l     = (const float*)d_in[5];
    const float* W_r     = (const float*)d_in[6];
    const float* gamma   = (const float*)d_in[7];
    const float* beta    = (const float*)d_in[8];
    const float* W_out   = (const float*)d_in[9];
    const float* b_out   = (const float*)d_in[10];
    const void* edge     = d_in[11];
    const void* batch_v  = d_in[12];
    const void* batch_p  = d_in[13];
    float* out = (float*)d_out;

    void* p;
    cudaGetSymbolAddress(&p, g_x);     float* x0 = (float*)p;
    cudaGetSymbolAddress(&p, g_accb);  float* a0 = (float*)p;
    cudaGetSymbolAddress(&p, g_tmpb);  __nv_bfloat16* tmpb = (__nv_bfloat16*)p;
    cudaGetSymbolAddress(&p, g_xb);    __nv_bfloat16* xb = (__nv_bfloat16*)p;
    cudaGetSymbolAddress(&p, g_inb);   __nv_bfloat16* inb = (__nv_bfloat16*)p;
    cudaGetSymbolAddress(&p, g_web);   __nv_bfloat16* web = (__nv_bfloat16*)p;
    cudaGetSymbolAddress(&p, g_wcat);  __nv_bfloat16* wcat = (__nv_bfloat16*)p;
    cudaGetSymbolAddress(&p, g_blsum); float* bls = (float*)p;
    cudaGetSymbolAddress(&p, g_deg);   void* degp = p;
    cudaGetSymbolAddress(&p, g_z);     void* zbase = p;
    float* zstats = (float*)zbase;
    float* zpool  = zstats + LL * 2 * 2 * HH;
    int*   zpcnt  = (int*)(zpool + 2 * GG * HH);

    cudaFuncSetAttribute(k_gemm, cudaFuncAttributeMaxDynamicSharedMemorySize, SMEM_G);

    // zero everything (deg + stats/pool/pcnt struct)
    cudaMemsetAsync(degp, 0, sizeof(int) * NREL * NN, 0);
    cudaMemsetAsync(zbase, 0, sizeof(ZeroBlk), 0);

    // combined prep (detect + weights + input split); then CSR
    k_prep<<<20000, 256>>>((const unsigned int*)edge, x_vuln, x_patch, W_emb, W_l, W_r, b_l);
    k_hist<<<(NREL * EE + 255) / 256, 256>>>(edge);
    k_scan<<<NREL, 1024>>>();
    k_fill<<<(NREL * EE + 255) / 256, 256>>>(edge);
    k_pcnt<<<(2 * NN + 255) / 256, 256>>>(batch_v, batch_p, zpcnt);

    const int MB = (NN + 127) / 128;
    size_t xs = (size_t)NN * HH;
    // embedding GEMMs (K=128), both types in one launch
    k_gemm<<<dim3(MB, 2, 2), 256, SMEM_G>>>(inb, (long long)NN * DIN, web, (long long)HH * DIN,
                                            x0, (long long)xs, b_emb, HH,
                                            xb, (long long)xs, 0, 2, 1, NN, DIN);

    for (int layer = 0; layer < LL; layer++) {
        float* lstats = zstats + layer * 2 * 2 * HH;
        // merged self + 3-neighbor GEMM, both types in one launch
        k_gemm<<<dim3(MB, 8, 2), 256, SMEM_G>>>(xb, (long long)xs,
                                                wcat + (size_t)(layer * 2) * 1024 * HH,
                                                (long long)1024 * HH,
                                                a0, (long long)xs, bls + layer * 2 * HH, HH,
                                                tmpb, (long long)3 * xs, (long long)xs,
                                                2, 0, NN, HH);
        // gather-mean + fused BN stats (both types)
        k_agg<<<dim3((NN * 32 + 255) / 256, 2), 256>>>(a0, lstats);
        if (layer < LL - 1) {
            k_bnapply<<<dim3(256, 2), 256>>>(a0, x0, xb, lstats,
                                             gamma + layer * 2 * HH, beta + layer * 2 * HH,
                                             layer > 0);
        } else {
            k_bnpool<<<dim3((NN + 63) / 64, 2), 256>>>(a0, x0, lstats,
                                                       gamma + layer * 2 * HH,
                                                       beta + layer * 2 * HH,
                                                       batch_v, batch_p, zpool);
        }
    }

    k_final<<<1, 1024>>>(W_out, b_out, zpool, zpcnt, out);
}

// round 15
// speedup vs baseline: 1.5093x; 1.0494x over previous
#include <cuda_runtime.h>
#include <cuda_bf16.h>
#include <math.h>
#include <stdint.h>

#define NN   20000
#define EE   320000
#define DIN  128
#define HH   256
#define LL   2
#define GG   32
#define NREL 6

// ---------------- device scratch ----------------
__device__ float g_x[2 * NN * HH];
__device__ float g_accb[2 * NN * HH];
__device__ uint8_t g_tmpf[NREL * NN * HH];          // neighbor GEMM outputs (fp8 e4m3)
__device__ __nv_bfloat16 g_xb[2 * NN * HH];
__device__ __nv_bfloat16 g_inb[2 * NN * DIN];
__device__ __nv_bfloat16 g_web[2 * HH * DIN];
__device__ __nv_bfloat16 g_wcat[LL * 2 * 1024 * HH];
__device__ float g_blsum[LL * 2 * HH];
__device__ int   g_deg[NREL][NN];
__device__ int   g_rowptr[NREL][NN + 1];
__device__ int   g_cursor[NREL][NN];
__device__ int   g_col[NREL][EE];
struct ZeroBlk {
    float stats[LL * 2 * 2 * HH];
    float pool[2 * GG * HH];
    int   pcnt[2 * GG];
};
__device__ ZeroBlk g_z;
__device__ int g_is64;

// ---------------- helpers ----------------
__device__ __forceinline__ int idx_at(const void* p, long long i, int is64) {
    return is64 ? (int)((const long long*)p)[i] : ((const int*)p)[i];
}
__device__ __forceinline__ uint32_t smem_u32(const void* p) {
    uint32_t a;
    asm("{ .reg .u64 t; cvta.to.shared.u64 t, %1; cvt.u32.u64 %0, t; }" : "=r"(a) : "l"(p));
    return a;
}
__device__ __forceinline__ void ldm_x4(uint32_t* r, uint32_t addr) {
    asm volatile("ldmatrix.sync.aligned.m8n8.x4.shared.b16 {%0,%1,%2,%3}, [%4];"
                 : "=r"(r[0]), "=r"(r[1]), "=r"(r[2]), "=r"(r[3]) : "r"(addr));
}
__device__ __forceinline__ void mma_bf16(float* c, const uint32_t* a, const uint32_t* b) {
    asm volatile("mma.sync.aligned.m16n8k16.row.col.f32.bf16.bf16.f32 "
                 "{%0,%1,%2,%3}, {%4,%5,%6,%7}, {%8,%9}, {%0,%1,%2,%3};"
                 : "+f"(c[0]), "+f"(c[1]), "+f"(c[2]), "+f"(c[3])
                 : "r"(a[0]), "r"(a[1]), "r"(a[2]), "r"(a[3]), "r"(b[0]), "r"(b[1]));
}
__device__ __forceinline__ void cp16(uint32_t dst, const void* src, int nbytes) {
    asm volatile("cp.async.cg.shared.global [%0], [%1], 16, %2;"
                 :: "r"(dst), "l"(src), "r"(nbytes));
}
// pack two f32 into e4m3x2 (low byte = v0, high byte = v1)
__device__ __forceinline__ unsigned short pack_e4m3x2(float v0, float v1) {
    unsigned short pk;
    asm("cvt.rn.satfinite.e4m3x2.f32 %0, %1, %2;" : "=h"(pk) : "f"(v1), "f"(v0));
    return pk;
}
// accumulate 8 fp8 values (uint2) into s[0..7]
__device__ __forceinline__ void addv8(float* s, uint2 v) {
#pragma unroll
    for (int w = 0; w < 2; w++) {
        uint32_t word = w ? v.y : v.x;
#pragma unroll
        for (int h = 0; h < 2; h++) {
            unsigned short pk = (unsigned short)(word >> (h * 16));
            uint32_t f16p;
            asm("cvt.rn.f16x2.e4m3x2 %0, %1;" : "=r"(f16p) : "h"(pk));
            __half2 hh = *reinterpret_cast<__half2*>(&f16p);
            float2 f = __half22float2(hh);
            int bi = w * 4 + h * 2;
            s[bi] += f.x;
            s[bi + 1] += f.y;
        }
    }
}

// ---------------- combined prep: dtype detect + weight prep + input split ----------------
__global__ void k_prep(const unsigned int* __restrict__ e,
                       const float* __restrict__ xv, const float* __restrict__ xp,
                       const float* __restrict__ We, const float* __restrict__ Wl,
                       const float* __restrict__ Wr, const float* __restrict__ bl) {
    const int grp[2][3] = {{0, 1, 3}, {2, 4, 5}};
    int gid = blockIdx.x * blockDim.x + threadIdx.x;

    if (blockIdx.x == 0) {
        __shared__ int any;
        if (threadIdx.x == 0) any = 0;
        __syncthreads();
        unsigned int v = 0;
        for (int i = threadIdx.x; i < 2048; i += blockDim.x)
            v |= e[(long long)i * 1874 + 1];
        if (v) any = 1;
        __syncthreads();
        if (threadIdx.x == 0) g_is64 = any ? 0 : 1;
    }

    if (gid < 2 * NN * DIN) {
        float s = (gid < NN * DIN) ? xv[gid] : xp[gid - NN * DIN];
        g_inb[gid] = __float2bfloat16(s);
    }
    if (gid < 2 * HH * DIN) {
        int t = gid >> 15, rem = gid & 32767, n = rem >> 7, k = rem & 127;
        g_web[t * HH * DIN + n * DIN + k] =
            __float2bfloat16(We[((long long)t * DIN + k) * HH + n]);
    }
    if (gid < LL * 2 * 1024 * HH) {
        int lt = gid >> 18, rem = gid & 0x3FFFF, row = rem >> 8, k = rem & 255;
        int layer = lt >> 1, t = lt & 1;
        float v;
        if (row < 256) {
            int n = row;
            const float* W = Wr + (long long)layer * NREL * HH * HH;
            v = W[(long long)grp[t][0] * HH * HH + k * HH + n] +
                W[(long long)grp[t][1] * HH * HH + k * HH + n] +
                W[(long long)grp[t][2] * HH * HH + k * HH + n];
        } else {
            int q = (row - 256) >> 8, n = row & 255;
            int rel = t * 3 + q;
            v = Wl[(((long long)layer * NREL + rel) * HH + k) * HH + n];
        }
        g_wcat[(long long)lt * 1024 * HH + row * HH + k] = __float2bfloat16(v);
    }
    if (gid < LL * 2 * HH) {
        int lt = gid >> 8, c = gid & 255;
        int layer = lt >> 1, t = lt & 1;
        const float* b = bl + (long long)layer * NREL * HH;
        g_blsum[lt * HH + c] = b[grp[t][0] * HH + c] + b[grp[t][1] * HH + c] +
                               b[grp[t][2] * HH + c];
    }
}

// ---------------- CSR construction ----------------
__global__ void k_hist(const void* __restrict__ edge) {
    int is64 = g_is64;
    int gid = blockIdx.x * blockDim.x + threadIdx.x;
    if (gid >= NREL * EE) return;
    int r = gid / EE, e = gid - r * EE;
    int dst = idx_at(edge, ((long long)r * 2 + 1) * EE + e, is64);
    atomicAdd(&g_deg[r][dst], 1);
}

__global__ void __launch_bounds__(1024) k_scan() {
    int r = blockIdx.x;
    const int PER = 20;
    int tid = threadIdx.x;
    int lane = tid & 31, wid = tid >> 5;
    int start = tid * PER;
    int loc[PER];
    int sum = 0;
#pragma unroll
    for (int i = 0; i < PER; i++) {
        int idx = start + i;
        int v = (idx < NN) ? g_deg[r][idx] : 0;
        loc[i] = sum;
        sum += v;
    }
    __shared__ int wsum[32];
    int incl = sum;
#pragma unroll
    for (int o = 1; o < 32; o <<= 1) {
        int x = __shfl_up_sync(0xffffffffu, incl, o);
        if (lane >= o) incl += x;
    }
    if (lane == 31) wsum[wid] = incl;
    __syncthreads();
    if (wid == 0) {
        int v = wsum[lane];
#pragma unroll
        for (int o = 1; o < 32; o <<= 1) {
            int x = __shfl_up_sync(0xffffffffu, v, o);
            if (lane >= o) v += x;
        }
        wsum[lane] = v;
    }
    __syncthreads();
    int prefix = incl - sum + (wid ? wsum[wid - 1] : 0);
#pragma unroll
    for (int i = 0; i < PER; i++) {
        int idx = start + i;
        if (idx < NN) {
            int ex = prefix + loc[i];
            g_rowptr[r][idx] = ex;
            g_cursor[r][idx] = ex;
        }
    }
    if (tid == 1023) g_rowptr[r][NN] = prefix + sum;
}

__global__ void k_fill(const void* __restrict__ edge) {
    int is64 = g_is64;
    int gid = blockIdx.x * blockDim.x + threadIdx.x;
    if (gid >= NREL * EE) return;
    int r = gid / EE, e = gid - r * EE;
    int src = idx_at(edge, ((long long)r * 2 + 0) * EE + e, is64);
    int dst = idx_at(edge, ((long long)r * 2 + 1) * EE + e, is64);
    int slot = atomicAdd(&g_cursor[r][dst], 1);
    g_col[r][slot] = src;
}

// ---------------- HMMA GEMM (bf16x1, BK=64, cp.async double-buffered) ----------------
#define SPAD2 72
#define BUFB (128 * SPAD2 * 2)
#define SMEM_G (4 * BUFB)

__global__ void __launch_bounds__(256, 2) k_gemm(
    const __nv_bfloat16* __restrict__ A0, long long aStr,
    const __nv_bfloat16* __restrict__ B0, long long bStr,
    float* __restrict__ Cf0, long long cfStr,
    const float* __restrict__ bias0, int biasStr,
    __nv_bfloat16* __restrict__ Xb0, long long xbzStr,
    uint8_t* __restrict__ F80, long long f8zStr, long long f8Stride,
    int selfN, int dualOut, int M, int K)
{
    extern __shared__ __nv_bfloat16 sm[];
    int z = blockIdx.z;
    const __nv_bfloat16* A = A0 + (long long)z * aStr;
    const __nv_bfloat16* B = B0 + (long long)z * bStr;
    float* Cf = Cf0 ? Cf0 + (long long)z * cfStr : nullptr;
    const float* bias = bias0 ? bias0 + (long long)z * biasStr : nullptr;
    __nv_bfloat16* Xb = Xb0 ? Xb0 + (long long)z * xbzStr : nullptr;
    uint8_t* F8z = F80 ? F80 + (long long)z * f8zStr : nullptr;

    int tid = threadIdx.x, wid = tid >> 5, lane = tid & 31;
    long long bm = (long long)blockIdx.x * 128;
    int nb = blockIdx.y * 128;
    int wm = (wid & 3) * 32;
    int wn = (wid >> 2) * 64;
    uint32_t sbA = smem_u32(sm);
    uint32_t sbB = sbA + 2 * BUFB;

    float acc[2][8][4];
#pragma unroll
    for (int i = 0; i < 2; i++)
#pragma unroll
        for (int j = 0; j < 8; j++)
#pragma unroll
            for (int q = 0; q < 4; q++) acc[i][j][q] = 0.0f;

    int a_row = (lane & 7) + ((lane >> 3) & 1) * 8;
    int a_col = (lane >> 4) * 8;
    int b_row = lane & 7;
    int b_col = (lane >> 3) * 8;
    int nch = K >> 6;

#define ISSUE_STAGE(c, buf) do {                                                    \
        _Pragma("unroll")                                                           \
        for (int i = tid; i < 1024; i += 256) {                                     \
            int row = i >> 3, seg = (i & 7) << 3;                                   \
            uint32_t so = (buf) * BUFB + (uint32_t)(row * SPAD2 + seg) * 2;         \
            int av = (bm + row < M) ? 16 : 0;                                       \
            const __nv_bfloat16* ga = A + ((bm + row < M) ?                         \
                                           ((bm + row) * K + (c) * 64 + seg) : 0);  \
            const __nv_bfloat16* gb = B + ((long long)(nb + row) * K + (c) * 64 + seg); \
            cp16(sbA + so, ga, av);                                                 \
            cp16(sbB + so, gb, 16);                                                 \
        }                                                                           \
        asm volatile("cp.async.commit_group;");                                     \
    } while (0)

    ISSUE_STAGE(0, 0);
    for (int c = 0; c < nch; c++) {
        if (c + 1 < nch) {
            ISSUE_STAGE(c + 1, (c + 1) & 1);
            asm volatile("cp.async.wait_group 1;");
        } else {
            asm volatile("cp.async.wait_group 0;");
        }
        __syncthreads();

        uint32_t bA = sbA + (c & 1) * BUFB, bB = sbB + (c & 1) * BUFB;
#pragma unroll
        for (int half = 0; half < 2; half++) {
            uint32_t bf[8][4];
#pragma unroll
            for (int nt = 0; nt < 8; nt++)
                ldm_x4(bf[nt], bB + (uint32_t)((wn + nt * 8 + b_row) * SPAD2 +
                                               half * 32 + b_col) * 2);
#pragma unroll
            for (int ks = 0; ks < 2; ks++) {
                uint32_t af[2][4];
#pragma unroll
                for (int mt = 0; mt < 2; mt++)
                    ldm_x4(af[mt], bA + (uint32_t)((wm + mt * 16 + a_row) * SPAD2 +
                                                   half * 32 + ks * 16 + a_col) * 2);
#pragma unroll
                for (int mt = 0; mt < 2; mt++)
#pragma unroll
                    for (int nt = 0; nt < 8; nt++)
                        mma_bf16(acc[mt][nt], af[mt], &bf[nt][ks * 2]);
            }
        }
        __syncthreads();
    }
#undef ISSUE_STAGE

    // ---- epilogue ----
    bool isSelf = (int)blockIdx.y < selfN;
    uint8_t* F8 = (!isSelf && F8z) ? (F8z + (long long)((blockIdx.y >> 1) - 1) * f8Stride) : nullptr;
    int gidr = lane >> 2, tig = lane & 3;
#pragma unroll
    for (int mt = 0; mt < 2; mt++) {
        long long r0 = bm + wm + mt * 16 + gidr;
        long long r1 = r0 + 8;
#pragma unroll
        for (int nt = 0; nt < 8; nt++) {
            int col = (blockIdx.y & 1) * 128 + wn + nt * 8 + tig * 2;
            float b0 = 0.f, b1 = 0.f;
            if (isSelf && bias) { b0 = bias[col]; b1 = bias[col + 1]; }
            if (r0 < M) {
                float v0 = acc[mt][nt][0] + b0, v1 = acc[mt][nt][1] + b1;
                if (isSelf) {
                    *(float2*)&Cf[r0 * 256 + col] = make_float2(v0, v1);
                    if (dualOut) *(__nv_bfloat162*)&Xb[r0 * 256 + col] = __floats2bfloat162_rn(v0, v1);
                } else {
                    *(unsigned short*)&F8[r0 * 256 + col] = pack_e4m3x2(v0, v1);
                }
            }
            if (r1 < M) {
                float v2 = acc[mt][nt][2] + b0, v3 = acc[mt][nt][3] + b1;
                if (isSelf) {
                    *(float2*)&Cf[r1 * 256 + col] = make_float2(v2, v3);
                    if (dualOut) *(__nv_bfloat162*)&Xb[r1 * 256 + col] = __floats2bfloat162_rn(v2, v3);
                } else {
                    *(unsigned short*)&F8[r1 * 256 + col] = pack_e4m3x2(v2, v3);
                }
            }
        }
    }
}

// ---------------- gather-mean aggregation (fp8 source) + fused BN stats ----------------
__global__ void k_agg(float* __restrict__ acc0, float* __restrict__ stats0) {
    __shared__ float bsum[HH], bsq[HH];
    int tid = threadIdx.x;
    int t = blockIdx.y;
    for (int i = tid; i < HH; i += 256) { bsum[i] = 0.f; bsq[i] = 0.f; }
    __syncthreads();

    int w = (blockIdx.x * blockDim.x + tid) >> 5;
    int lane = tid & 31;
    const int grp[2][3] = {{0, 1, 3}, {2, 4, 5}};
    float* acc = acc0 + (long long)t * NN * HH;
    float* stats = stats0 + t * 2 * HH;

    if (w < NN) {
        float s3[8] = {0.f, 0.f, 0.f, 0.f, 0.f, 0.f, 0.f, 0.f};
#pragma unroll
        for (int q = 0; q < 3; q++) {
            int r = grp[t][q];
            int b = g_rowptr[r][w], e = g_rowptr[r][w + 1];
            float s[8] = {0.f, 0.f, 0.f, 0.f, 0.f, 0.f, 0.f, 0.f};
            const uint2* base = (const uint2*)(g_tmpf + (long long)r * NN * HH);
            for (int j0 = b; j0 < e; j0 += 32) {
                int n = min(32, e - j0);
                int myc = (lane < n) ? g_col[r][j0 + lane] : 0;
                int k = 0;
                for (; k + 3 < n; k += 4) {
                    int c0 = __shfl_sync(0xffffffffu, myc, k);
                    int c1 = __shfl_sync(0xffffffffu, myc, k + 1);
                    int c2 = __shfl_sync(0xffffffffu, myc, k + 2);
                    int c3 = __shfl_sync(0xffffffffu, myc, k + 3);
                    uint2 v0 = base[(long long)c0 * 32 + lane];
                    uint2 v1 = base[(long long)c1 * 32 + lane];
                    uint2 v2 = base[(long long)c2 * 32 + lane];
                    uint2 v3 = base[(long long)c3 * 32 + lane];
                    addv8(s, v0); addv8(s, v1); addv8(s, v2); addv8(s, v3);
                }
                for (; k < n; k++) {
                    int c0 = __shfl_sync(0xffffffffu, myc, k);
                    uint2 v0 = base[(long long)c0 * 32 + lane];
                    addv8(s, v0);
                }
            }
            float inv = (e > b) ? 1.0f / (float)(e - b) : 0.0f;
#pragma unroll
            for (int u = 0; u < 8; u++) s3[u] = fmaf(s[u], inv, s3[u]);
        }
        float4* arow = (float4*)(acc + (long long)w * HH + lane * 8);
        float4 o0 = arow[0], o1 = arow[1];
        float fin[8] = {o0.x + s3[0], o0.y + s3[1], o0.z + s3[2], o0.w + s3[3],
                        o1.x + s3[4], o1.y + s3[5], o1.z + s3[6], o1.w + s3[7]};
        arow[0] = make_float4(fin[0], fin[1], fin[2], fin[3]);
        arow[1] = make_float4(fin[4], fin[5], fin[6], fin[7]);
#pragma unroll
        for (int u = 0; u < 8; u++) {
            atomicAdd(&bsum[lane * 8 + u], fin[u]);
            atomicAdd(&bsq[lane * 8 + u], fin[u] * fin[u]);
        }
    }
    __syncthreads();
    for (int i = tid; i < HH; i += 256) {
        atomicAdd(&stats[i], bsum[i]);
        atomicAdd(&stats[HH + i], bsq[i]);
    }
}

// ---------------- batchnorm apply (non-final layers) ----------------
__global__ void k_bnapply(const float* __restrict__ acc0, float* __restrict__ x0,
                          __nv_bfloat16* __restrict__ xb0,
                          const float* __restrict__ st0, const float* __restrict__ gamma0,
                          const float* __restrict__ beta0, int resid) {
    int t = blockIdx.y;
    long long off = (long long)t * NN * HH;
    const float* acc = acc0 + off;
    float* x = x0 + off;
    __nv_bfloat16* xb = xb0 + off;
    const float* st = st0 + t * 2 * HH;
    const float* gamma = gamma0 + t * HH;
    const float* beta  = beta0 + t * HH;
    int c = threadIdx.x;
    float meanA = st[c] * (1.0f / NN);
    float varA  = st[HH + c] * (1.0f / NN) - meanA * meanA;
    float varX  = varA * (1.0f / 9.0f);
    float rs    = rsqrtf(varX + 1e-5f);
    float scale = gamma[c] * rs * (1.0f / 3.0f);
    float shift = beta[c] - meanA * scale;
    for (int r = blockIdx.x; r < NN; r += gridDim.x) {
        long long i = (long long)r * HH + c;
        float y = fmaxf(fmaf(acc[i], scale, shift), 0.0f);
        float xn = resid ? (x[i] + y) : y;
        x[i] = xn;
        xb[i] = __float2bfloat16(xn);
    }
}

// ---------------- final layer: BN + residual + mean pool, fused ----------------
__global__ void k_bnpool(const float* __restrict__ acc0, const float* __restrict__ x0,
                         const float* __restrict__ st0, const float* __restrict__ gamma0,
                         const float* __restrict__ beta0,
                         const void* __restrict__ bv, const void* __restrict__ bp,
                         float* __restrict__ pool0) {
    int is64 = g_is64;
    int t = blockIdx.y;
    long long off = (long long)t * NN * HH;
    const float* acc = acc0 + off;
    const float* x = x0 + off;
    const float* st = st0 + t * 2 * HH;
    const void* batch = t ? bp : bv;
    float* pool = pool0 + t * GG * HH;
    int c = threadIdx.x;
    float meanA = st[c] * (1.0f / NN);
    float varA  = st[HH + c] * (1.0f / NN) - meanA * meanA;
    float rs    = rsqrtf(varA * (1.0f / 9.0f) + 1e-5f);
    float scale = gamma0[t * HH + c] * rs * (1.0f / 3.0f);
    float shift = beta0[t * HH + c] - meanA * scale;

    int r0 = blockIdx.x * 64;
    int r1 = min(r0 + 64, NN);
    float local = 0.f;
    int gprev = -1;
    for (int r = r0; r < r1; r++) {
        int g = idx_at(batch, r, is64);
        if (g != gprev) {
            if (gprev >= 0) atomicAdd(&pool[gprev * HH + c], local);
            local = 0.f;
            gprev = g;
        }
        long long i = (long long)r * HH + c;
        float y = fmaxf(fmaf(acc[i], scale, shift), 0.0f);
        local += x[i] + y;
    }
    if (gprev >= 0) atomicAdd(&pool[gprev * HH + c], local);
}

// ---------------- pcnt + head ----------------
__global__ void k_pcnt(const void* __restrict__ bv, const void* __restrict__ bp,
                       int* __restrict__ pcnt) {
    int is64 = g_is64;
    int gid = blockIdx.x * blockDim.x + threadIdx.x;
    if (gid >= 2 * NN) return;
    int t = gid / NN, i = gid - t * NN;
    int g = t ? idx_at(bp, i, is64) : idx_at(bv, i, is64);
    atomicAdd(&pcnt[t * GG + g], 1);
}

__global__ void k_final(const float* __restrict__ Wo, const float* __restrict__ bo,
                        const float* __restrict__ pool, const int* __restrict__ pcnt,
                        float* __restrict__ out) {
    int g = threadIdx.x >> 5, lane = threadIdx.x & 31;
    if (g >= GG) return;
    float cv = (float)max(pcnt[g], 1);
    float cp = (float)max(pcnt[GG + g], 1);
    float s = 0.f;
    for (int c = lane; c < HH; c += 32)
        s += pool[g * HH + c] / cv * Wo[c] + pool[GG * HH + g * HH + c] / cp * Wo[HH + c];
#pragma unroll
    for (int off = 16; off; off >>= 1) s += __shfl_down_sync(0xffffffffu, s, off);
    if (lane == 0) out[g] = 1.0f / (1.0f + expf(-(s + bo[0])));
}

// ---------------- launcher ----------------
extern "C" void kernel_launch(void* const* d_in, const int* in_sizes, int n_in,
                              void* d_out, int out_size) {
    const float* x_vuln  = (const float*)d_in[0];
    const float* x_patch = (const float*)d_in[1];
    const float* W_emb   = (const float*)d_in[2];
    const float* b_emb   = (const float*)d_in[3];
    const float* W_l     = (const float*)d_in[4];
    const float* b_l     = (const float*)d_in[5];
    const float* W_r     = (const float*)d_in[6];
    const float* gamma   = (const float*)d_in[7];
    const float* beta    = (const float*)d_in[8];
    const float* W_out   = (const float*)d_in[9];
    const float* b_out   = (const float*)d_in[10];
    const void* edge     = d_in[11];
    const void* batch_v  = d_in[12];
    const void* batch_p  = d_in[13];
    float* out = (float*)d_out;

    void* p;
    cudaGetSymbolAddress(&p, g_x);     float* x0 = (float*)p;
    cudaGetSymbolAddress(&p, g_accb);  float* a0 = (float*)p;
    cudaGetSymbolAddress(&p, g_tmpf);  uint8_t* tmpf = (uint8_t*)p;
    cudaGetSymbolAddress(&p, g_xb);    __nv_bfloat16* xb = (__nv_bfloat16*)p;
    cudaGetSymbolAddress(&p, g_inb);   __nv_bfloat16* inb = (__nv_bfloat16*)p;
    cudaGetSymbolAddress(&p, g_web);   __nv_bfloat16* web = (__nv_bfloat16*)p;
    cudaGetSymbolAddress(&p, g_wcat);  __nv_bfloat16* wcat = (__nv_bfloat16*)p;
    cudaGetSymbolAddress(&p, g_blsum); float* bls = (float*)p;
    cudaGetSymbolAddress(&p, g_deg);   void* degp = p;
    cudaGetSymbolAddress(&p, g_z);     void* zbase = p;
    float* zstats = (float*)zbase;
    float* zpool  = zstats + LL * 2 * 2 * HH;
    int*   zpcnt  = (int*)(zpool + 2 * GG * HH);

    cudaFuncSetAttribute(k_gemm, cudaFuncAttributeMaxDynamicSharedMemorySize, SMEM_G);

    cudaMemsetAsync(degp, 0, sizeof(int) * NREL * NN, 0);
    cudaMemsetAsync(zbase, 0, sizeof(ZeroBlk), 0);

    k_prep<<<20000, 256>>>((const unsigned int*)edge, x_vuln, x_patch, W_emb, W_l, W_r, b_l);
    k_hist<<<(NREL * EE + 255) / 256, 256>>>(edge);
    k_scan<<<NREL, 1024>>>();
    k_fill<<<(NREL * EE + 255) / 256, 256>>>(edge);
    k_pcnt<<<(2 * NN + 255) / 256, 256>>>(batch_v, batch_p, zpcnt);

    const int MB = (NN + 127) / 128;
    size_t xs = (size_t)NN * HH;
    // embedding GEMMs (K=128), both types in one launch (all-self, dual fp32+bf16 out)
    k_gemm<<<dim3(MB, 2, 2), 256, SMEM_G>>>(inb, (long long)NN * DIN, web, (long long)HH * DIN,
                                            x0, (long long)xs, b_emb, HH,
                                            xb, (long long)xs,
                                            nullptr, 0, 0,
                                            2, 1, NN, DIN);

    for (int layer = 0; layer < LL; layer++) {
        float* lstats = zstats + layer * 2 * 2 * HH;
        // merged self(fp32) + 3-neighbor(fp8) GEMM, both types in one launch
        k_gemm<<<dim3(MB, 8, 2), 256, SMEM_G>>>(xb, (long long)xs,
                                                wcat + (size_t)(layer * 2) * 1024 * HH,
                                                (long long)1024 * HH,
                                                a0, (long long)xs, bls + layer * 2 * HH, HH,
                                                nullptr, 0,
                                                tmpf, (long long)3 * xs, (long long)xs,
                                                2, 0, NN, HH);
        // gather-mean (fp8) + fused BN stats (both types)
        k_agg<<<dim3((NN * 32 + 255) / 256, 2), 256>>>(a0, lstats);
        if (layer < LL - 1) {
            k_bnapply<<<dim3(256, 2), 256>>>(a0, x0, xb, lstats,
                                             gamma + layer * 2 * HH, beta + layer * 2 * HH,
                                             layer > 0);
        } else {
            k_bnpool<<<dim3((NN + 63) / 64, 2), 256>>>(a0, x0, lstats,
                                                       gamma + layer * 2 * HH,
                                                       beta + layer * 2 * HH,
                                                       batch_v, batch_p, zpool);
        }
    }

    k_final<<<1, 1024>>>(W_out, b_out, zpool, zpcnt, out);
}